// round 14
// baseline (speedup 1.0000x reference)
#include <cuda_runtime.h>
#include <math.h>

#define NB   8
#define NN   4096
#define HID  16
#define BUFN 56

__device__ __align__(16) float g_h1[NB*64*NN];
__device__ __align__(16) float g_nodes[NB*NN*HID];
__device__ __align__(16) float g_sq[NB*NN];          // 0.5*|node|^2
__device__ __align__(16) float g_xp[NB*NN*HID];
__device__ __align__(16) float g_asr[NB*NN*4];
__device__ __align__(16) float g_adt[NB*NN*4];
__device__ __align__(16) float g_p[NB*NN*HID];
__device__ __align__(16) float g_outlow[NB*NN];

__device__ __forceinline__ unsigned long long ffma2(unsigned long long a,
                                                    unsigned long long b,
                                                    unsigned long long c) {
    unsigned long long d;
    asm("fma.rn.f32x2 %0, %1, %2, %3;" : "=l"(d) : "l"(a), "l"(b), "l"(c));
    return d;
}
__device__ __forceinline__ unsigned long long pk2(float lo, float hi) {
    unsigned long long u;
    asm("mov.b64 %0, {%1, %2};" : "=l"(u) : "r"(__float_as_uint(lo)), "r"(__float_as_uint(hi)));
    return u;
}
__device__ __forceinline__ void unpk(unsigned long long u, float& a, float& b) {
    asm("mov.b64 {%0, %1}, %2;" : "=f"(a), "=f"(b) : "l"(u));
}

// ---------- fused bilinear 256->64 + conv1 + BN + ReLU ----------
__global__ void __launch_bounds__(256) downconv1k(
    const float* __restrict__ x,
    const float* __restrict__ W1, const float* __restrict__ b1,
    const float* __restrict__ g1, const float* __restrict__ be1,
    const float* __restrict__ m1, const float* __restrict__ v1)
{
    __shared__ __align__(16) float sw[576];
    __shared__ __align__(16) float sb[64];
    __shared__ float sa[64];
    __shared__ float sxl[324];
    int t = threadIdx.x;
    int b = blockIdx.y;
    int y0 = (blockIdx.x >> 2) * 16, x0 = (blockIdx.x & 3) * 16;
    if (t < 64) {
        float a = g1[t] / sqrtf(v1[t] + 1e-5f);
        sa[t] = a;
        sb[t] = (b1[t] - m1[t]) * a + be1[t];
    }
    __syncthreads();
    for (int i = t; i < 576; i += 256) {
        int oc = i & 63, tp = i >> 6;
        sw[i] = W1[oc*9 + tp] * sa[oc];
    }
    const float* src = x + (size_t)b * 65536;
    for (int i = t; i < 324; i += 256) {
        int rr = i / 18, cc = i - rr*18;
        int oy = y0 + rr - 1, ox = x0 + cc - 1;
        float val = 0.f;
        if (oy >= 0 && oy < 64 && ox >= 0 && ox < 64) {
            float wy[8], wx[8]; float sy = 0.f, sx = 0.f;
            #pragma unroll
            for (int d = 0; d < 8; d++) {
                float w = 1.f - 0.25f * fabsf((float)d - 3.5f);
                int jy = 4*oy + d - 2, jx = 4*ox + d - 2;
                wy[d] = (jy >= 0 && jy < 256) ? w : 0.f; sy += wy[d];
                wx[d] = (jx >= 0 && jx < 256) ? w : 0.f; sx += wx[d];
            }
            float acc = 0.f;
            #pragma unroll
            for (int dy = 0; dy < 8; dy++) {
                int jy = 4*oy + dy - 2; jy = jy < 0 ? 0 : (jy > 255 ? 255 : jy);
                float ra = 0.f;
                #pragma unroll
                for (int dx = 0; dx < 8; dx++) {
                    int jx = 4*ox + dx - 2; jx = jx < 0 ? 0 : (jx > 255 ? 255 : jx);
                    ra = fmaf(wx[dx], src[jy*256 + jx], ra);
                }
                acc = fmaf(wy[dy], ra, acc);
            }
            val = acc / (sy * sx);
        }
        sxl[i] = val;
    }
    __syncthreads();
    int ty = t >> 4, tx = t & 15;
    float vin[9];
    #pragma unroll
    for (int dy = 0; dy < 3; dy++)
        #pragma unroll
        for (int dx = 0; dx < 3; dx++)
            vin[dy*3+dx] = sxl[(ty+dy)*18 + (tx+dx)];
    int y = y0 + ty, xx = x0 + tx;
    const float4* sw4 = (const float4*)sw;
    const float4* sb4 = (const float4*)sb;
    size_t base = ((size_t)b*64)*4096 + y*64 + xx;
    #pragma unroll
    for (int o4 = 0; o4 < 16; o4++) {
        float4 a = sb4[o4];
        #pragma unroll
        for (int tp = 0; tp < 9; tp++) {
            float v = vin[tp];
            float4 wv = sw4[tp*16 + o4];
            a.x = fmaf(v, wv.x, a.x); a.y = fmaf(v, wv.y, a.y);
            a.z = fmaf(v, wv.z, a.z); a.w = fmaf(v, wv.w, a.w);
        }
        g_h1[base + (size_t)(o4*4    )*4096] = fmaxf(a.x, 0.f);
        g_h1[base + (size_t)(o4*4 + 1)*4096] = fmaxf(a.y, 0.f);
        g_h1[base + (size_t)(o4*4 + 2)*4096] = fmaxf(a.z, 0.f);
        g_h1[base + (size_t)(o4*4 + 3)*4096] = fmaxf(a.w, 0.f);
    }
}

// ---------- conv2 64->16, 16x16 tile, 4 oc per block ----------
__global__ void __launch_bounds__(256) conv2k(
    const float* __restrict__ W2, const float* __restrict__ b2,
    const float* __restrict__ g2, const float* __restrict__ be2,
    const float* __restrict__ m2, const float* __restrict__ v2)
{
    __shared__ __align__(16) float swt[2304];
    __shared__ __align__(16) float tile[16*324];
    __shared__ float sA[16];
    __shared__ float sbeta[4];
    int t = threadIdx.x;
    int tilei = blockIdx.x, oq = blockIdx.y, b = blockIdx.z;
    int y0 = (tilei >> 2) * 16, x0 = (tilei & 3) * 16;
    if (t < 16) sA[t] = g2[t] / sqrtf(v2[t] + 1e-5f);
    __syncthreads();
    if (t < 4) {
        int oc = oq*4 + t;
        sbeta[t] = (b2[oc] - m2[oc]) * sA[oc] + be2[oc];
    }
    for (int e = t; e < 2304; e += 256) {
        int o = e & 3; int r = e >> 2; int tp = r % 9; int ci = r / 9;
        int oc = oq*4 + o;
        swt[e] = W2[(oc*64 + ci)*9 + tp] * sA[oc];
    }
    int ty = t >> 4, tx = t & 15;
    float a0 = 0.f, a1 = 0.f, a2 = 0.f, a3 = 0.f;
    for (int cc = 0; cc < 4; cc++) {
        __syncthreads();
        for (int i = t; i < 5184; i += 256) {
            int cl = i / 324; int rem = i - cl*324; int rr = rem / 18; int c = rem - rr*18;
            int yy = y0 + rr - 1, xc = x0 + c - 1;
            float v = 0.f;
            if (yy >= 0 && yy < 64 && xc >= 0 && xc < 64)
                v = g_h1[(((size_t)b*64 + (cc*16 + cl))*64 + yy)*64 + xc];
            tile[i] = v;
        }
        __syncthreads();
        #pragma unroll
        for (int cl = 0; cl < 16; cl++) {
            int ci = cc*16 + cl;
            float v[9];
            #pragma unroll
            for (int dy = 0; dy < 3; dy++)
                #pragma unroll
                for (int dx = 0; dx < 3; dx++)
                    v[dy*3+dx] = tile[cl*324 + (ty+dy)*18 + (tx+dx)];
            const float4* w4 = (const float4*)&swt[ci*36];
            #pragma unroll
            for (int tp = 0; tp < 9; tp++) {
                float vv = v[tp];
                float4 w = w4[tp];
                a0 = fmaf(vv, w.x, a0); a1 = fmaf(vv, w.y, a1);
                a2 = fmaf(vv, w.z, a2); a3 = fmaf(vv, w.w, a3);
            }
        }
    }
    a0 = fmaxf(a0 + sbeta[0], 0.f);
    a1 = fmaxf(a1 + sbeta[1], 0.f);
    a2 = fmaxf(a2 + sbeta[2], 0.f);
    a3 = fmaxf(a3 + sbeta[3], 0.f);
    int n = (y0 + ty)*64 + (x0 + tx);
    float4* dst = (float4*)&g_nodes[((size_t)b*NN + n)*16 + oq*4];
    dst[0] = make_float4(a0, a1, a2, a3);
}

// ---------- GAT transform + 0.5|n|^2 ----------
__global__ void featk(const float* __restrict__ Wg, const float* __restrict__ a_src,
                      const float* __restrict__ a_dst)
{
    __shared__ float sWg[256];
    __shared__ float ssrc[16], sdst[16];
    int t = threadIdx.x;
    sWg[t] = Wg[t];
    if (t < 16) { ssrc[t] = a_src[t]; sdst[t] = a_dst[t]; }
    __syncthreads();
    int idx = blockIdx.x * 256 + t;
    const float4* np = (const float4*)&g_nodes[(size_t)idx*16];
    float n[16];
    float4 v0 = np[0], v1 = np[1], v2 = np[2], v3 = np[3];
    n[0]=v0.x; n[1]=v0.y; n[2]=v0.z; n[3]=v0.w;
    n[4]=v1.x; n[5]=v1.y; n[6]=v1.z; n[7]=v1.w;
    n[8]=v2.x; n[9]=v2.y; n[10]=v2.z; n[11]=v2.w;
    n[12]=v3.x; n[13]=v3.y; n[14]=v3.z; n[15]=v3.w;
    float s = 0.f;
    #pragma unroll
    for (int c = 0; c < 16; c++) s = fmaf(n[c], n[c], s);
    g_sq[idx] = 0.5f * s;
    float xo[16];
    #pragma unroll
    for (int o = 0; o < 16; o++) {
        float a = 0.f;
        #pragma unroll
        for (int c = 0; c < 16; c++) a = fmaf(n[c], sWg[o*16 + c], a);
        xo[o] = a;
    }
    float4* xpd = (float4*)&g_xp[(size_t)idx*16];
    xpd[0] = make_float4(xo[0],xo[1],xo[2],xo[3]);
    xpd[1] = make_float4(xo[4],xo[5],xo[6],xo[7]);
    xpd[2] = make_float4(xo[8],xo[9],xo[10],xo[11]);
    xpd[3] = make_float4(xo[12],xo[13],xo[14],xo[15]);
    float av0=0,av1=0,av2=0,av3=0,dv0=0,dv1=0,dv2=0,dv3=0;
    #pragma unroll
    for (int c = 0; c < 4; c++) {
        av0 = fmaf(xo[c],    ssrc[c],    av0); dv0 = fmaf(xo[c],    sdst[c],    dv0);
        av1 = fmaf(xo[4+c],  ssrc[4+c],  av1); dv1 = fmaf(xo[4+c],  sdst[4+c],  dv1);
        av2 = fmaf(xo[8+c],  ssrc[8+c],  av2); dv2 = fmaf(xo[8+c],  sdst[8+c],  dv2);
        av3 = fmaf(xo[12+c], ssrc[12+c], av3); dv3 = fmaf(xo[12+c], sdst[12+c], dv3);
    }
    ((float4*)g_asr)[idx] = make_float4(av0,av1,av2,av3);
    ((float4*)g_adt)[idx] = make_float4(dv0,dv1,dv2,dv3);
}

// ---------- warp-collective lex top-8 flush: buf[0..n) -> buf[0..7] sorted ----------
__device__ __forceinline__ void flushrow(float2* buf, int& cnt, float& d8, int& i8, int lane)
{
    int n = cnt;
    #pragma unroll 1
    for (int k = 0; k < 8; k++) {
        float md = 3e38f; int mj = 0x7fffffff; int mp = 0;
        for (int q = lane; q < n; q += 32) {
            float2 e = buf[q];
            int ej = __float_as_int(e.y);
            if (e.x < md || (e.x == md && ej < mj)) { md = e.x; mj = ej; mp = q; }
        }
        #pragma unroll
        for (int m = 16; m >= 1; m >>= 1) {
            float od = __shfl_xor_sync(0xffffffffu, md, m);
            int   oj = __shfl_xor_sync(0xffffffffu, mj, m);
            int   op = __shfl_xor_sync(0xffffffffu, mp, m);
            if (od < md || (od == md && oj < mj)) { md = od; mj = oj; mp = op; }
        }
        if (lane == 0) {
            buf[mp] = make_float2(3e38f, __int_as_float(0x7fffffff));
            buf[48 + k] = make_float2(md, __int_as_float(mj));
        }
        __syncwarp();
    }
    if (lane < 8) buf[lane] = buf[48 + lane];
    __syncwarp();
    float2 e8 = buf[7];
    d8 = e8.x; i8 = __float_as_int(e8.y);
    cnt = 8;
}

// serial GAT for one row (runs per-lane, uniform control flow)
__device__ void gat_one(int row, int b, const float2* rb, const float* __restrict__ bg)
{
    size_t nb_ = (size_t)b*NN;
    float4 adv = ((const float4*)g_adt)[nb_ + row];
    int idxs[9];
    #pragma unroll
    for (int k = 0; k < 8; k++) idxs[k] = __float_as_int(rb[k].y);
    idxs[8] = row;
    float lg[36];
    float m0 = -3e38f, m1 = -3e38f, m2 = -3e38f, m3 = -3e38f;
    #pragma unroll
    for (int k = 0; k < 9; k++) {
        float4 av = ((const float4*)g_asr)[nb_ + idxs[k]];
        float l0 = av.x + adv.x; l0 = l0 > 0.f ? l0 : 0.2f*l0;
        float l1 = av.y + adv.y; l1 = l1 > 0.f ? l1 : 0.2f*l1;
        float l2 = av.z + adv.z; l2 = l2 > 0.f ? l2 : 0.2f*l2;
        float l3 = av.w + adv.w; l3 = l3 > 0.f ? l3 : 0.2f*l3;
        lg[k*4+0]=l0; lg[k*4+1]=l1; lg[k*4+2]=l2; lg[k*4+3]=l3;
        m0 = fmaxf(m0,l0); m1 = fmaxf(m1,l1); m2 = fmaxf(m2,l2); m3 = fmaxf(m3,l3);
    }
    float s0=0,s1=0,s2=0,s3=0;
    float out[16];
    #pragma unroll
    for (int c = 0; c < 16; c++) out[c] = 0.f;
    #pragma unroll
    for (int k = 0; k < 9; k++) {
        float w0 = expf(lg[k*4+0]-m0), w1 = expf(lg[k*4+1]-m1);
        float w2 = expf(lg[k*4+2]-m2), w3 = expf(lg[k*4+3]-m3);
        s0 += w0; s1 += w1; s2 += w2; s3 += w3;
        const float4* xp4 = (const float4*)g_xp + (nb_ + idxs[k])*4;
        float4 x0 = xp4[0], x1 = xp4[1], x2 = xp4[2], x3 = xp4[3];
        out[0]  = fmaf(w0,x0.x,out[0]);  out[1]  = fmaf(w0,x0.y,out[1]);
        out[2]  = fmaf(w0,x0.z,out[2]);  out[3]  = fmaf(w0,x0.w,out[3]);
        out[4]  = fmaf(w1,x1.x,out[4]);  out[5]  = fmaf(w1,x1.y,out[5]);
        out[6]  = fmaf(w1,x1.z,out[6]);  out[7]  = fmaf(w1,x1.w,out[7]);
        out[8]  = fmaf(w2,x2.x,out[8]);  out[9]  = fmaf(w2,x2.y,out[9]);
        out[10] = fmaf(w2,x2.z,out[10]); out[11] = fmaf(w2,x2.w,out[11]);
        out[12] = fmaf(w3,x3.x,out[12]); out[13] = fmaf(w3,x3.y,out[13]);
        out[14] = fmaf(w3,x3.z,out[14]); out[15] = fmaf(w3,x3.w,out[15]);
    }
    float i0 = 1.f/s0, i1 = 1.f/s1, i2 = 1.f/s2, i3 = 1.f/s3;
    float4* pd = (float4*)g_p + (nb_ + row)*4;
    pd[0] = make_float4(fmaxf(out[0]*i0+bg[0],0.f),  fmaxf(out[1]*i0+bg[1],0.f),
                        fmaxf(out[2]*i0+bg[2],0.f),  fmaxf(out[3]*i0+bg[3],0.f));
    pd[1] = make_float4(fmaxf(out[4]*i1+bg[4],0.f),  fmaxf(out[5]*i1+bg[5],0.f),
                        fmaxf(out[6]*i1+bg[6],0.f),  fmaxf(out[7]*i1+bg[7],0.f));
    pd[2] = make_float4(fmaxf(out[8]*i2+bg[8],0.f),  fmaxf(out[9]*i2+bg[9],0.f),
                        fmaxf(out[10]*i2+bg[10],0.f),fmaxf(out[11]*i2+bg[11],0.f));
    pd[3] = make_float4(fmaxf(out[12]*i3+bg[12],0.f),fmaxf(out[13]*i3+bg[13],0.f),
                        fmaxf(out[14]*i3+bg[14],0.f),fmaxf(out[15]*i3+bg[15],0.f));
}

// ---------- kNN top-8 + GAT: candidate-per-lane, warp = 8 rows ----------
__global__ void __launch_bounds__(256) knnk(const float* __restrict__ bg)
{
    __shared__ __align__(16) unsigned long long srow[32*16];  // (-r0k,-r1k) pairs, 4 KB
    __shared__ __align__(8)  float2 sbuf[64*BUFN];            // 28 KB
    __shared__ int sseq[128];
    int t = threadIdx.x, lane = t & 31, w = t >> 5;
    int b = blockIdx.y;
    int rowbase = blockIdx.x * 64;       // block = image row y = blockIdx.x
    const float* nbase = g_nodes + (size_t)b*NN*16;
    const float* sqb = g_sq + (size_t)b*NN;

    if (t == 0) {                        // proximity chunk order (chunk = 32 cands)
        int y = blockIdx.x;
        int lo = y, hi = y, idx = 0;
        sseq[idx++] = 2*y; sseq[idx++] = 2*y + 1;
        while (idx < 128) {
            if (hi < 63) { hi++; sseq[idx++] = 2*hi; sseq[idx++] = 2*hi + 1; }
            if (lo > 0 && idx < 128) { lo--; sseq[idx++] = 2*lo; sseq[idx++] = 2*lo + 1; }
        }
    }
    // stage negated rows pair-interleaved
    for (int i = t; i < 1024; i += 256) {
        int row = i >> 4, k = i & 15;
        float v = nbase[(size_t)(rowbase + row)*16 + k];
        ((float*)srow)[((row >> 1)*16 + k)*2 + (row & 1)] = -v;
    }
    __syncthreads();

    float2* bufw = sbuf + (size_t)w*8*BUFN;
    float d8[8]; int i8[8]; int cnt[8];
    #pragma unroll
    for (int r = 0; r < 8; r++) { d8[r] = 3e38f; i8[r] = 0x7fffffff; cnt[r] = 0; }
    int rw = rowbase + w*8;
    unsigned lmask = (1u << lane) - 1u;

    for (int u = 0; u < 128; u++) {
        int tile = sseq[u];
        int cidx = tile*32 + lane;
        const float4* cp = (const float4*)(nbase + (size_t)cidx*16);
        float4 q0 = cp[0], q1 = cp[1], q2 = cp[2], q3 = cp[3];
        unsigned long long cd[16];
        cd[0]=pk2(q0.x,q0.x); cd[1]=pk2(q0.y,q0.y); cd[2]=pk2(q0.z,q0.z); cd[3]=pk2(q0.w,q0.w);
        cd[4]=pk2(q1.x,q1.x); cd[5]=pk2(q1.y,q1.y); cd[6]=pk2(q1.z,q1.z); cd[7]=pk2(q1.w,q1.w);
        cd[8]=pk2(q2.x,q2.x); cd[9]=pk2(q2.y,q2.y); cd[10]=pk2(q2.z,q2.z); cd[11]=pk2(q2.w,q2.w);
        cd[12]=pk2(q3.x,q3.x); cd[13]=pk2(q3.y,q3.y); cd[14]=pk2(q3.z,q3.z); cd[15]=pk2(q3.w,q3.w);
        float csq = sqb[cidx];
        unsigned long long csq2 = pk2(csq, csq);
        #pragma unroll
        for (int p = 0; p < 4; p++) {
            const ulonglong2* rp2 = (const ulonglong2*)srow + (w*4 + p)*8;
            ulonglong2 a0 = rp2[0], a1 = rp2[1], a2 = rp2[2], a3 = rp2[3];
            ulonglong2 a4 = rp2[4], a5 = rp2[5], a6 = rp2[6], a7 = rp2[7];
            unsigned long long acc = csq2;
            acc = ffma2(a0.x, cd[0],  acc); acc = ffma2(a0.y, cd[1],  acc);
            acc = ffma2(a1.x, cd[2],  acc); acc = ffma2(a1.y, cd[3],  acc);
            acc = ffma2(a2.x, cd[4],  acc); acc = ffma2(a2.y, cd[5],  acc);
            acc = ffma2(a3.x, cd[6],  acc); acc = ffma2(a3.y, cd[7],  acc);
            acc = ffma2(a4.x, cd[8],  acc); acc = ffma2(a4.y, cd[9],  acc);
            acc = ffma2(a5.x, cd[10], acc); acc = ffma2(a5.y, cd[11], acc);
            acc = ffma2(a6.x, cd[12], acc); acc = ffma2(a6.y, cd[13], acc);
            acc = ffma2(a7.x, cd[14], acc); acc = ffma2(a7.y, cd[15], acc);
            float s0, s1; unpk(acc, s0, s1);
            int r0 = p*2, r1 = p*2 + 1;
            bool h0 = (s0 < d8[r0] || (s0 == d8[r0] && cidx < i8[r0])) && (cidx != rw + r0);
            bool h1 = (s1 < d8[r1] || (s1 == d8[r1] && cidx < i8[r1])) && (cidx != rw + r1);
            unsigned b0 = __ballot_sync(0xffffffffu, h0);
            unsigned b1 = __ballot_sync(0xffffffffu, h1);
            if (h0) bufw[r0*BUFN + cnt[r0] + __popc(b0 & lmask)] = make_float2(s0, __int_as_float(cidx));
            cnt[r0] += __popc(b0);
            if (h1) bufw[r1*BUFN + cnt[r1] + __popc(b1 & lmask)] = make_float2(s1, __int_as_float(cidx));
            cnt[r1] += __popc(b1);
        }
        __syncwarp();
        #pragma unroll
        for (int r = 0; r < 8; r++)
            if (cnt[r] > 16) flushrow(bufw + r*BUFN, cnt[r], d8[r], i8[r], lane);
    }
    #pragma unroll
    for (int r = 0; r < 8; r++)
        flushrow(bufw + r*BUFN, cnt[r], d8[r], i8[r], lane);
    __syncwarp();
    if (lane < 8) gat_one(rw + lane, b, bufw + lane*BUFN, bg);
}

// ---------- update MLP + fire + out conv + sigmoid ----------
__global__ void updk(const float* __restrict__ fire, const float* __restrict__ Wu1,
                     const float* __restrict__ bu1, const float* __restrict__ Wu2,
                     const float* __restrict__ bu2,
                     const float* __restrict__ Wo,  const float* __restrict__ bo)
{
    __shared__ __align__(16) float sW1[2048];
    __shared__ __align__(16) float sW2[2048];
    __shared__ float sb1[128], sb2[16], sWo[16];
    __shared__ float sbo;
    int t = threadIdx.x;
    for (int i = t; i < 2048; i += 256) {
        sW1[i] = Wu1[i];
        int h = i >> 4, o = i & 15;
        sW2[i] = Wu2[o*128 + h];
    }
    if (t < 128) sb1[t] = bu1[t];
    if (t < 16)  { sb2[t] = bu2[t]; sWo[t] = Wo[t]; }
    if (t == 0)  sbo = bo[0];
    __syncthreads();
    int idx = blockIdx.x * 256 + t;
    const float4* pp = (const float4*)(g_p + (size_t)idx*16);
    float4 p0 = pp[0], p1 = pp[1], p2 = pp[2], p3 = pp[3];
    float p[16];
    p[0]=p0.x; p[1]=p0.y; p[2]=p0.z; p[3]=p0.w;
    p[4]=p1.x; p[5]=p1.y; p[6]=p1.z; p[7]=p1.w;
    p[8]=p2.x; p[9]=p2.y; p[10]=p2.z; p[11]=p2.w;
    p[12]=p3.x; p[13]=p3.y; p[14]=p3.z; p[15]=p3.w;
    float u[16];
    #pragma unroll
    for (int o = 0; o < 16; o++) u[o] = sb2[o];
    #pragma unroll 2
    for (int h = 0; h < 128; h++) {
        float a = sb1[h];
        const float4* w1p = (const float4*)&sW1[h*16];
        float4 wa = w1p[0], wb = w1p[1], wc = w1p[2], wd = w1p[3];
        a = fmaf(p[0],wa.x,a); a = fmaf(p[1],wa.y,a); a = fmaf(p[2],wa.z,a); a = fmaf(p[3],wa.w,a);
        a = fmaf(p[4],wb.x,a); a = fmaf(p[5],wb.y,a); a = fmaf(p[6],wb.z,a); a = fmaf(p[7],wb.w,a);
        a = fmaf(p[8],wc.x,a); a = fmaf(p[9],wc.y,a); a = fmaf(p[10],wc.z,a); a = fmaf(p[11],wc.w,a);
        a = fmaf(p[12],wd.x,a); a = fmaf(p[13],wd.y,a); a = fmaf(p[14],wd.z,a); a = fmaf(p[15],wd.w,a);
        a = fmaxf(a, 0.f);
        const float4* w2p = (const float4*)&sW2[h*16];
        float4 va = w2p[0], vb = w2p[1], vc = w2p[2], vd = w2p[3];
        u[0]  = fmaf(a,va.x,u[0]);  u[1]  = fmaf(a,va.y,u[1]);
        u[2]  = fmaf(a,va.z,u[2]);  u[3]  = fmaf(a,va.w,u[3]);
        u[4]  = fmaf(a,vb.x,u[4]);  u[5]  = fmaf(a,vb.y,u[5]);
        u[6]  = fmaf(a,vb.z,u[6]);  u[7]  = fmaf(a,vb.w,u[7]);
        u[8]  = fmaf(a,vc.x,u[8]);  u[9]  = fmaf(a,vc.y,u[9]);
        u[10] = fmaf(a,vc.z,u[10]); u[11] = fmaf(a,vc.w,u[11]);
        u[12] = fmaf(a,vd.x,u[12]); u[13] = fmaf(a,vd.y,u[13]);
        u[14] = fmaf(a,vd.z,u[14]); u[15] = fmaf(a,vd.w,u[15]);
    }
    float mask = fire[idx] < 0.5f ? 1.f : 0.f;
    const float4* hp = (const float4*)(g_nodes + (size_t)idx*16);
    float4 h0 = hp[0], h1 = hp[1], h2 = hp[2], h3 = hp[3];
    float hh[16];
    hh[0]=h0.x; hh[1]=h0.y; hh[2]=h0.z; hh[3]=h0.w;
    hh[4]=h1.x; hh[5]=h1.y; hh[6]=h1.z; hh[7]=h1.w;
    hh[8]=h2.x; hh[9]=h2.y; hh[10]=h2.z; hh[11]=h2.w;
    hh[12]=h3.x; hh[13]=h3.y; hh[14]=h3.z; hh[15]=h3.w;
    float ss = sbo;
    #pragma unroll
    for (int c = 0; c < 16; c++) {
        float hn = fmaf(mask, u[c], hh[c]);
        ss = fmaf(sWo[c], hn, ss);
    }
    g_outlow[idx] = 1.f / (1.f + expf(-ss));
}

// ---------- bilinear 64 -> 256 ----------
__global__ void upk(float* __restrict__ out)
{
    int idx = blockIdx.x * 256 + threadIdx.x;
    int b = idx >> 16, oy = (idx >> 8) & 255, ox = idx & 255;
    float sy = (oy + 0.5f) * 0.25f - 0.5f;
    float sx = (ox + 0.5f) * 0.25f - 0.5f;
    int y0 = (int)floorf(sy); float fy = sy - (float)y0;
    int x0 = (int)floorf(sx); float fx = sx - (float)x0;
    float wy0 = 1.f - fy, wy1 = fy; int y1 = y0 + 1;
    float wx0 = 1.f - fx, wx1 = fx; int x1 = x0 + 1;
    if (y0 < 0)  { wy0 = 0.f; y0 = 0; }
    if (y1 > 63) { wy1 = 0.f; y1 = 63; }
    if (x0 < 0)  { wx0 = 0.f; x0 = 0; }
    if (x1 > 63) { wx1 = 0.f; x1 = 63; }
    const float* src = g_outlow + b * 4096;
    float v = wy0 * (wx0 * src[y0*64 + x0] + wx1 * src[y0*64 + x1])
            + wy1 * (wx0 * src[y1*64 + x0] + wx1 * src[y1*64 + x1]);
    out[idx] = v / ((wy0 + wy1) * (wx0 + wx1));
}

extern "C" void kernel_launch(void* const* d_in, const int* in_sizes, int n_in,
                              void* d_out, int out_size)
{
    (void)in_sizes; (void)n_in; (void)out_size;
    const float* x    = (const float*)d_in[0];
    const float* fire = (const float*)d_in[1];
    const float* W1   = (const float*)d_in[2];
    const float* b1   = (const float*)d_in[3];
    const float* g1   = (const float*)d_in[4];
    const float* be1  = (const float*)d_in[5];
    const float* m1   = (const float*)d_in[6];
    const float* v1   = (const float*)d_in[7];
    const float* W2   = (const float*)d_in[8];
    const float* b2   = (const float*)d_in[9];
    const float* g2   = (const float*)d_in[10];
    const float* be2  = (const float*)d_in[11];
    const float* m2   = (const float*)d_in[12];
    const float* v2   = (const float*)d_in[13];
    const float* Wg   = (const float*)d_in[14];
    const float* a_src= (const float*)d_in[15];
    const float* a_dst= (const float*)d_in[16];
    const float* bg   = (const float*)d_in[17];
    const float* Wu1  = (const float*)d_in[18];
    const float* bu1  = (const float*)d_in[19];
    const float* Wu2  = (const float*)d_in[20];
    const float* bu2  = (const float*)d_in[21];
    const float* Wo   = (const float*)d_in[22];
    const float* bo   = (const float*)d_in[23];
    float* out = (float*)d_out;

    downconv1k<<<dim3(16, NB), 256>>>(x, W1, b1, g1, be1, m1, v1);
    conv2k<<<dim3(16, 4, NB), 256>>>(W2, b2, g2, be2, m2, v2);
    featk<<<128, 256>>>(Wg, a_src, a_dst);
    knnk<<<dim3(64, NB), 256>>>(bg);
    updk<<<128, 256>>>(fire, Wu1, bu1, Wu2, bu2, Wo, bo);
    upk<<<2048, 256>>>(out);
}

// round 15
// speedup vs baseline: 1.8108x; 1.8108x over previous
#include <cuda_runtime.h>
#include <math.h>

#define NB   8
#define NN   4096
#define HID  16

__device__ __align__(16) float g_h1[NB*64*NN];
__device__ __align__(16) float g_nodes[NB*NN*HID];
__device__ __align__(16) float g_sq[NB*NN];          // 0.5*|node|^2
__device__ __align__(16) float g_xp[NB*NN*HID];
__device__ __align__(16) float g_asr[NB*NN*4];
__device__ __align__(16) float g_adt[NB*NN*4];
__device__ __align__(16) float g_p[NB*NN*HID];
__device__ __align__(16) float g_outlow[NB*NN];

__device__ __forceinline__ unsigned long long ffma2(unsigned long long a,
                                                    unsigned long long b,
                                                    unsigned long long c) {
    unsigned long long d;
    asm("fma.rn.f32x2 %0, %1, %2, %3;" : "=l"(d) : "l"(a), "l"(b), "l"(c));
    return d;
}
__device__ __forceinline__ unsigned long long pk2(float lo, float hi) {
    unsigned long long u;
    asm("mov.b64 %0, {%1, %2};" : "=l"(u) : "r"(__float_as_uint(lo)), "r"(__float_as_uint(hi)));
    return u;
}
__device__ __forceinline__ void unpk(unsigned long long u, float& a, float& b) {
    asm("mov.b64 {%0, %1}, %2;" : "=f"(a), "=f"(b) : "l"(u));
}

// ---------- fused bilinear 256->64 + conv1 + BN + ReLU ----------
__global__ void __launch_bounds__(256) downconv1k(
    const float* __restrict__ x,
    const float* __restrict__ W1, const float* __restrict__ b1,
    const float* __restrict__ g1, const float* __restrict__ be1,
    const float* __restrict__ m1, const float* __restrict__ v1)
{
    __shared__ __align__(16) float sw[576];
    __shared__ __align__(16) float sb[64];
    __shared__ float sa[64];
    __shared__ float sxl[324];
    int t = threadIdx.x;
    int b = blockIdx.y;
    int y0 = (blockIdx.x >> 2) * 16, x0 = (blockIdx.x & 3) * 16;
    if (t < 64) {
        float a = g1[t] / sqrtf(v1[t] + 1e-5f);
        sa[t] = a;
        sb[t] = (b1[t] - m1[t]) * a + be1[t];
    }
    __syncthreads();
    for (int i = t; i < 576; i += 256) {
        int oc = i & 63, tp = i >> 6;
        sw[i] = W1[oc*9 + tp] * sa[oc];
    }
    const float* src = x + (size_t)b * 65536;
    for (int i = t; i < 324; i += 256) {
        int rr = i / 18, cc = i - rr*18;
        int oy = y0 + rr - 1, ox = x0 + cc - 1;
        float val = 0.f;
        if (oy >= 0 && oy < 64 && ox >= 0 && ox < 64) {
            float wy[8], wx[8]; float sy = 0.f, sx = 0.f;
            #pragma unroll
            for (int d = 0; d < 8; d++) {
                float w = 1.f - 0.25f * fabsf((float)d - 3.5f);
                int jy = 4*oy + d - 2, jx = 4*ox + d - 2;
                wy[d] = (jy >= 0 && jy < 256) ? w : 0.f; sy += wy[d];
                wx[d] = (jx >= 0 && jx < 256) ? w : 0.f; sx += wx[d];
            }
            float acc = 0.f;
            #pragma unroll
            for (int dy = 0; dy < 8; dy++) {
                int jy = 4*oy + dy - 2; jy = jy < 0 ? 0 : (jy > 255 ? 255 : jy);
                float ra = 0.f;
                #pragma unroll
                for (int dx = 0; dx < 8; dx++) {
                    int jx = 4*ox + dx - 2; jx = jx < 0 ? 0 : (jx > 255 ? 255 : jx);
                    ra = fmaf(wx[dx], src[jy*256 + jx], ra);
                }
                acc = fmaf(wy[dy], ra, acc);
            }
            val = acc / (sy * sx);
        }
        sxl[i] = val;
    }
    __syncthreads();
    int ty = t >> 4, tx = t & 15;
    float vin[9];
    #pragma unroll
    for (int dy = 0; dy < 3; dy++)
        #pragma unroll
        for (int dx = 0; dx < 3; dx++)
            vin[dy*3+dx] = sxl[(ty+dy)*18 + (tx+dx)];
    int y = y0 + ty, xx = x0 + tx;
    const float4* sw4 = (const float4*)sw;
    const float4* sb4 = (const float4*)sb;
    size_t base = ((size_t)b*64)*4096 + y*64 + xx;
    #pragma unroll
    for (int o4 = 0; o4 < 16; o4++) {
        float4 a = sb4[o4];
        #pragma unroll
        for (int tp = 0; tp < 9; tp++) {
            float v = vin[tp];
            float4 wv = sw4[tp*16 + o4];
            a.x = fmaf(v, wv.x, a.x); a.y = fmaf(v, wv.y, a.y);
            a.z = fmaf(v, wv.z, a.z); a.w = fmaf(v, wv.w, a.w);
        }
        g_h1[base + (size_t)(o4*4    )*4096] = fmaxf(a.x, 0.f);
        g_h1[base + (size_t)(o4*4 + 1)*4096] = fmaxf(a.y, 0.f);
        g_h1[base + (size_t)(o4*4 + 2)*4096] = fmaxf(a.z, 0.f);
        g_h1[base + (size_t)(o4*4 + 3)*4096] = fmaxf(a.w, 0.f);
    }
}

// ---------- conv2 64->16, 16x16 tile, 4 oc per block ----------
__global__ void __launch_bounds__(256) conv2k(
    const float* __restrict__ W2, const float* __restrict__ b2,
    const float* __restrict__ g2, const float* __restrict__ be2,
    const float* __restrict__ m2, const float* __restrict__ v2)
{
    __shared__ __align__(16) float swt[2304];
    __shared__ __align__(16) float tile[16*324];
    __shared__ float sA[16];
    __shared__ float sbeta[4];
    int t = threadIdx.x;
    int tilei = blockIdx.x, oq = blockIdx.y, b = blockIdx.z;
    int y0 = (tilei >> 2) * 16, x0 = (tilei & 3) * 16;
    if (t < 16) sA[t] = g2[t] / sqrtf(v2[t] + 1e-5f);
    __syncthreads();
    if (t < 4) {
        int oc = oq*4 + t;
        sbeta[t] = (b2[oc] - m2[oc]) * sA[oc] + be2[oc];
    }
    for (int e = t; e < 2304; e += 256) {
        int o = e & 3; int r = e >> 2; int tp = r % 9; int ci = r / 9;
        int oc = oq*4 + o;
        swt[e] = W2[(oc*64 + ci)*9 + tp] * sA[oc];
    }
    int ty = t >> 4, tx = t & 15;
    float a0 = 0.f, a1 = 0.f, a2 = 0.f, a3 = 0.f;
    for (int cc = 0; cc < 4; cc++) {
        __syncthreads();
        for (int i = t; i < 5184; i += 256) {
            int cl = i / 324; int rem = i - cl*324; int rr = rem / 18; int c = rem - rr*18;
            int yy = y0 + rr - 1, xc = x0 + c - 1;
            float v = 0.f;
            if (yy >= 0 && yy < 64 && xc >= 0 && xc < 64)
                v = g_h1[(((size_t)b*64 + (cc*16 + cl))*64 + yy)*64 + xc];
            tile[i] = v;
        }
        __syncthreads();
        #pragma unroll
        for (int cl = 0; cl < 16; cl++) {
            int ci = cc*16 + cl;
            float v[9];
            #pragma unroll
            for (int dy = 0; dy < 3; dy++)
                #pragma unroll
                for (int dx = 0; dx < 3; dx++)
                    v[dy*3+dx] = tile[cl*324 + (ty+dy)*18 + (tx+dx)];
            const float4* w4 = (const float4*)&swt[ci*36];
            #pragma unroll
            for (int tp = 0; tp < 9; tp++) {
                float vv = v[tp];
                float4 w = w4[tp];
                a0 = fmaf(vv, w.x, a0); a1 = fmaf(vv, w.y, a1);
                a2 = fmaf(vv, w.z, a2); a3 = fmaf(vv, w.w, a3);
            }
        }
    }
    a0 = fmaxf(a0 + sbeta[0], 0.f);
    a1 = fmaxf(a1 + sbeta[1], 0.f);
    a2 = fmaxf(a2 + sbeta[2], 0.f);
    a3 = fmaxf(a3 + sbeta[3], 0.f);
    int n = (y0 + ty)*64 + (x0 + tx);
    float4* dst = (float4*)&g_nodes[((size_t)b*NN + n)*16 + oq*4];
    dst[0] = make_float4(a0, a1, a2, a3);
}

// ---------- GAT transform + 0.5|n|^2 ----------
__global__ void featk(const float* __restrict__ Wg, const float* __restrict__ a_src,
                      const float* __restrict__ a_dst)
{
    __shared__ float sWg[256];
    __shared__ float ssrc[16], sdst[16];
    int t = threadIdx.x;
    sWg[t] = Wg[t];
    if (t < 16) { ssrc[t] = a_src[t]; sdst[t] = a_dst[t]; }
    __syncthreads();
    int idx = blockIdx.x * 256 + t;
    const float4* np = (const float4*)&g_nodes[(size_t)idx*16];
    float n[16];
    float4 v0 = np[0], v1 = np[1], v2 = np[2], v3 = np[3];
    n[0]=v0.x; n[1]=v0.y; n[2]=v0.z; n[3]=v0.w;
    n[4]=v1.x; n[5]=v1.y; n[6]=v1.z; n[7]=v1.w;
    n[8]=v2.x; n[9]=v2.y; n[10]=v2.z; n[11]=v2.w;
    n[12]=v3.x; n[13]=v3.y; n[14]=v3.z; n[15]=v3.w;
    float s = 0.f;
    #pragma unroll
    for (int c = 0; c < 16; c++) s = fmaf(n[c], n[c], s);
    g_sq[idx] = 0.5f * s;
    float xo[16];
    #pragma unroll
    for (int o = 0; o < 16; o++) {
        float a = 0.f;
        #pragma unroll
        for (int c = 0; c < 16; c++) a = fmaf(n[c], sWg[o*16 + c], a);
        xo[o] = a;
    }
    float4* xpd = (float4*)&g_xp[(size_t)idx*16];
    xpd[0] = make_float4(xo[0],xo[1],xo[2],xo[3]);
    xpd[1] = make_float4(xo[4],xo[5],xo[6],xo[7]);
    xpd[2] = make_float4(xo[8],xo[9],xo[10],xo[11]);
    xpd[3] = make_float4(xo[12],xo[13],xo[14],xo[15]);
    float av0=0,av1=0,av2=0,av3=0,dv0=0,dv1=0,dv2=0,dv3=0;
    #pragma unroll
    for (int c = 0; c < 4; c++) {
        av0 = fmaf(xo[c],    ssrc[c],    av0); dv0 = fmaf(xo[c],    sdst[c],    dv0);
        av1 = fmaf(xo[4+c],  ssrc[4+c],  av1); dv1 = fmaf(xo[4+c],  sdst[4+c],  dv1);
        av2 = fmaf(xo[8+c],  ssrc[8+c],  av2); dv2 = fmaf(xo[8+c],  sdst[8+c],  dv2);
        av3 = fmaf(xo[12+c], ssrc[12+c], av3); dv3 = fmaf(xo[12+c], sdst[12+c], dv3);
    }
    ((float4*)g_asr)[idx] = make_float4(av0,av1,av2,av3);
    ((float4*)g_adt)[idx] = make_float4(dv0,dv1,dv2,dv3);
}

// ---------- kNN top-8 + GAT: 1 row/thread, NO split, tau-seeded strict gate ----------
__global__ void __launch_bounds__(256) knnk(const float* __restrict__ bg)
{
    __shared__ __align__(16) float4 scand[512];   // 8 KB: 128 cands x 16 floats
    __shared__ float ssq[128];
    int t = threadIdx.x;
    int b = blockIdx.y;
    int row = blockIdx.x * 256 + t;
    const float* nbase = g_nodes + (size_t)b*NN*16;
    const float* sqb = g_sq + (size_t)b*NN;

    float nv[16];
    {
        const float4* rpp = (const float4*)(nbase + (size_t)row*16);
        float4 f0 = rpp[0], f1 = rpp[1], f2 = rpp[2], f3 = rpp[3];
        nv[0]=-f0.x; nv[1]=-f0.y; nv[2]=-f0.z; nv[3]=-f0.w;
        nv[4]=-f1.x; nv[5]=-f1.y; nv[6]=-f1.z; nv[7]=-f1.w;
        nv[8]=-f2.x; nv[9]=-f2.y; nv[10]=-f2.z; nv[11]=-f2.w;
        nv[12]=-f3.x; nv[13]=-f3.y; nv[14]=-f3.z; nv[15]=-f3.w;
    }

    // tau pre-pass (ALL threads): 8th-smallest over 24 spatial nbrs (5x5),
    // computed with the packed-equivalent accE/accO rounding -> exact bound.
    float tau;
    {
        float td[8];
        #pragma unroll
        for (int p = 0; p < 8; p++) td[p] = 3e38f;
        int y = row >> 6, x = row & 63;
        int sy = y - 2; sy = sy < 0 ? 0 : (sy > 59 ? 59 : sy);
        int sx = x - 2; sx = sx < 0 ? 0 : (sx > 59 ? 59 : sx);
        for (int dy = 0; dy < 5; dy++) {
            for (int dx = 0; dx < 5; dx++) {
                int n = (sy+dy)*64 + (sx+dx);
                if (n == row) continue;
                const float4* cp4 = (const float4*)(nbase + (size_t)n*16);
                float4 c0 = cp4[0], c1 = cp4[1], c2 = cp4[2], c3 = cp4[3];
                float aE = sqb[n], aO = 0.f;
                aE = fmaf(nv[0],  c0.x, aE); aO = fmaf(nv[1],  c0.y, aO);
                aE = fmaf(nv[2],  c0.z, aE); aO = fmaf(nv[3],  c0.w, aO);
                aE = fmaf(nv[4],  c1.x, aE); aO = fmaf(nv[5],  c1.y, aO);
                aE = fmaf(nv[6],  c1.z, aE); aO = fmaf(nv[7],  c1.w, aO);
                aE = fmaf(nv[8],  c2.x, aE); aO = fmaf(nv[9],  c2.y, aO);
                aE = fmaf(nv[10], c2.z, aE); aO = fmaf(nv[11], c2.w, aO);
                aE = fmaf(nv[12], c3.x, aE); aO = fmaf(nv[13], c3.y, aO);
                aE = fmaf(nv[14], c3.z, aE); aO = fmaf(nv[15], c3.w, aO);
                float acc = aE + aO;
                if (acc < td[7]) {
                    td[7] = acc;
                    #pragma unroll
                    for (int p = 7; p > 0; p--)
                        if (td[p] < td[p-1]) { float tmp = td[p]; td[p] = td[p-1]; td[p-1] = tmp; }
                }
            }
        }
        tau = td[7];
    }
    float gate0 = nextafterf(tau, 3.4e38f);     // acc < gate0 <=> acc <= tau
    float gate = gate0;

    unsigned long long rneg[8];
    #pragma unroll
    for (int q = 0; q < 8; q++) rneg[q] = pk2(nv[2*q], nv[2*q+1]);

    // seed: inserts only for strict sub-tau candidates; >=8 reals exist (spatial nbrs)
    float bd[8]; int bi[8];
    #pragma unroll
    for (int p = 0; p < 8; p++) { bd[p] = gate0; bi[p] = 0x3fffffff; }

    for (int tt = 0; tt < 32; tt++) {
        __syncthreads();
        {
            const float4* src = (const float4*)nbase + (size_t)(tt*128)*4;
            scand[t]       = src[t];
            scand[t + 256] = src[t + 256];
            if (t < 128) ssq[t] = sqb[tt*128 + t];
        }
        __syncthreads();
        int cb = tt * 128;
        const ulonglong2* fb = (const ulonglong2*)scand;
        #pragma unroll 4
        for (int j = 0; j < 128; j++) {
            ulonglong2 w0 = fb[j*4+0], w1 = fb[j*4+1], w2 = fb[j*4+2], w3 = fb[j*4+3];
            unsigned long long acc = pk2(ssq[j], 0.f);
            acc = ffma2(rneg[0], w0.x, acc); acc = ffma2(rneg[1], w0.y, acc);
            acc = ffma2(rneg[2], w1.x, acc); acc = ffma2(rneg[3], w1.y, acc);
            acc = ffma2(rneg[4], w2.x, acc); acc = ffma2(rneg[5], w2.y, acc);
            acc = ffma2(rneg[6], w3.x, acc); acc = ffma2(rneg[7], w3.y, acc);
            float lo, hi; unpk(acc, lo, hi);
            float d = lo + hi;
            if (d < gate) {                 // strict: equal-d later indices rejected
                int jj = cb + j;
                if (jj != row) {
                    bd[7] = d; bi[7] = jj;
                    #pragma unroll
                    for (int p = 7; p > 0; p--)
                        if (bd[p] < bd[p-1]) {
                            float tmp = bd[p]; bd[p] = bd[p-1]; bd[p-1] = tmp;
                            int ti = bi[p]; bi[p] = bi[p-1]; bi[p-1] = ti;
                        }
                    gate = bd[7];
                }
            }
        }
    }

    // ---- GAT aggregation over 8 neighbors + self (per-thread) ----
    float4 adv = ((const float4*)g_adt)[b*NN + row];
    float ad0 = adv.x, ad1 = adv.y, ad2 = adv.z, ad3 = adv.w;
    int idxs[9];
    #pragma unroll
    for (int k = 0; k < 8; k++) idxs[k] = bi[k];
    idxs[8] = row;
    float lg[36];
    float m0 = -3e38f, m1 = -3e38f, m2 = -3e38f, m3 = -3e38f;
    #pragma unroll
    for (int k = 0; k < 9; k++) {
        float4 av = ((const float4*)g_asr)[b*NN + idxs[k]];
        float l0 = av.x + ad0; l0 = l0 > 0.f ? l0 : 0.2f*l0;
        float l1 = av.y + ad1; l1 = l1 > 0.f ? l1 : 0.2f*l1;
        float l2 = av.z + ad2; l2 = l2 > 0.f ? l2 : 0.2f*l2;
        float l3 = av.w + ad3; l3 = l3 > 0.f ? l3 : 0.2f*l3;
        lg[k*4+0] = l0; lg[k*4+1] = l1; lg[k*4+2] = l2; lg[k*4+3] = l3;
        m0 = fmaxf(m0, l0); m1 = fmaxf(m1, l1); m2 = fmaxf(m2, l2); m3 = fmaxf(m3, l3);
    }
    float s0 = 0.f, s1 = 0.f, s2 = 0.f, s3 = 0.f;
    float out[16];
    #pragma unroll
    for (int c = 0; c < 16; c++) out[c] = 0.f;
    #pragma unroll
    for (int k = 0; k < 9; k++) {
        float w0 = expf(lg[k*4+0] - m0);
        float w1 = expf(lg[k*4+1] - m1);
        float w2 = expf(lg[k*4+2] - m2);
        float w3 = expf(lg[k*4+3] - m3);
        s0 += w0; s1 += w1; s2 += w2; s3 += w3;
        const float4* xp4 = (const float4*)g_xp + ((size_t)b*NN + idxs[k])*4;
        float4 x0 = xp4[0], x1 = xp4[1], x2 = xp4[2], x3 = xp4[3];
        out[0]  = fmaf(w0, x0.x, out[0]);  out[1]  = fmaf(w0, x0.y, out[1]);
        out[2]  = fmaf(w0, x0.z, out[2]);  out[3]  = fmaf(w0, x0.w, out[3]);
        out[4]  = fmaf(w1, x1.x, out[4]);  out[5]  = fmaf(w1, x1.y, out[5]);
        out[6]  = fmaf(w1, x1.z, out[6]);  out[7]  = fmaf(w1, x1.w, out[7]);
        out[8]  = fmaf(w2, x2.x, out[8]);  out[9]  = fmaf(w2, x2.y, out[9]);
        out[10] = fmaf(w2, x2.z, out[10]); out[11] = fmaf(w2, x2.w, out[11]);
        out[12] = fmaf(w3, x3.x, out[12]); out[13] = fmaf(w3, x3.y, out[13]);
        out[14] = fmaf(w3, x3.z, out[14]); out[15] = fmaf(w3, x3.w, out[15]);
    }
    float inv0 = 1.f/s0, inv1 = 1.f/s1, inv2 = 1.f/s2, inv3 = 1.f/s3;
    float res[16];
    #pragma unroll
    for (int c = 0; c < 4;  c++) res[c] = fmaxf(out[c]*inv0 + bg[c], 0.f);
    #pragma unroll
    for (int c = 4; c < 8;  c++) res[c] = fmaxf(out[c]*inv1 + bg[c], 0.f);
    #pragma unroll
    for (int c = 8; c < 12; c++) res[c] = fmaxf(out[c]*inv2 + bg[c], 0.f);
    #pragma unroll
    for (int c = 12; c < 16; c++) res[c] = fmaxf(out[c]*inv3 + bg[c], 0.f);
    float4* pd = (float4*)g_p + ((size_t)b*NN + row)*4;
    pd[0] = make_float4(res[0],res[1],res[2],res[3]);
    pd[1] = make_float4(res[4],res[5],res[6],res[7]);
    pd[2] = make_float4(res[8],res[9],res[10],res[11]);
    pd[3] = make_float4(res[12],res[13],res[14],res[15]);
}

// ---------- update MLP + fire + out conv + sigmoid ----------
__global__ void updk(const float* __restrict__ fire, const float* __restrict__ Wu1,
                     const float* __restrict__ bu1, const float* __restrict__ Wu2,
                     const float* __restrict__ bu2,
                     const float* __restrict__ Wo,  const float* __restrict__ bo)
{
    __shared__ __align__(16) float sW1[2048];
    __shared__ __align__(16) float sW2[2048];
    __shared__ float sb1[128], sb2[16], sWo[16];
    __shared__ float sbo;
    int t = threadIdx.x;
    for (int i = t; i < 2048; i += 256) {
        sW1[i] = Wu1[i];
        int h = i >> 4, o = i & 15;
        sW2[i] = Wu2[o*128 + h];
    }
    if (t < 128) sb1[t] = bu1[t];
    if (t < 16)  { sb2[t] = bu2[t]; sWo[t] = Wo[t]; }
    if (t == 0)  sbo = bo[0];
    __syncthreads();
    int idx = blockIdx.x * 256 + t;
    const float4* pp = (const float4*)(g_p + (size_t)idx*16);
    float4 p0 = pp[0], p1 = pp[1], p2 = pp[2], p3 = pp[3];
    float p[16];
    p[0]=p0.x; p[1]=p0.y; p[2]=p0.z; p[3]=p0.w;
    p[4]=p1.x; p[5]=p1.y; p[6]=p1.z; p[7]=p1.w;
    p[8]=p2.x; p[9]=p2.y; p[10]=p2.z; p[11]=p2.w;
    p[12]=p3.x; p[13]=p3.y; p[14]=p3.z; p[15]=p3.w;
    float u[16];
    #pragma unroll
    for (int o = 0; o < 16; o++) u[o] = sb2[o];
    #pragma unroll 2
    for (int h = 0; h < 128; h++) {
        float a = sb1[h];
        const float4* w1p = (const float4*)&sW1[h*16];
        float4 wa = w1p[0], wb = w1p[1], wc = w1p[2], wd = w1p[3];
        a = fmaf(p[0],wa.x,a); a = fmaf(p[1],wa.y,a); a = fmaf(p[2],wa.z,a); a = fmaf(p[3],wa.w,a);
        a = fmaf(p[4],wb.x,a); a = fmaf(p[5],wb.y,a); a = fmaf(p[6],wb.z,a); a = fmaf(p[7],wb.w,a);
        a = fmaf(p[8],wc.x,a); a = fmaf(p[9],wc.y,a); a = fmaf(p[10],wc.z,a); a = fmaf(p[11],wc.w,a);
        a = fmaf(p[12],wd.x,a); a = fmaf(p[13],wd.y,a); a = fmaf(p[14],wd.z,a); a = fmaf(p[15],wd.w,a);
        a = fmaxf(a, 0.f);
        const float4* w2p = (const float4*)&sW2[h*16];
        float4 va = w2p[0], vb = w2p[1], vc = w2p[2], vd = w2p[3];
        u[0]  = fmaf(a,va.x,u[0]);  u[1]  = fmaf(a,va.y,u[1]);
        u[2]  = fmaf(a,va.z,u[2]);  u[3]  = fmaf(a,va.w,u[3]);
        u[4]  = fmaf(a,vb.x,u[4]);  u[5]  = fmaf(a,vb.y,u[5]);
        u[6]  = fmaf(a,vb.z,u[6]);  u[7]  = fmaf(a,vb.w,u[7]);
        u[8]  = fmaf(a,vc.x,u[8]);  u[9]  = fmaf(a,vc.y,u[9]);
        u[10] = fmaf(a,vc.z,u[10]); u[11] = fmaf(a,vc.w,u[11]);
        u[12] = fmaf(a,vd.x,u[12]); u[13] = fmaf(a,vd.y,u[13]);
        u[14] = fmaf(a,vd.z,u[14]); u[15] = fmaf(a,vd.w,u[15]);
    }
    float mask = fire[idx] < 0.5f ? 1.f : 0.f;
    const float4* hp = (const float4*)(g_nodes + (size_t)idx*16);
    float4 h0 = hp[0], h1 = hp[1], h2 = hp[2], h3 = hp[3];
    float hh[16];
    hh[0]=h0.x; hh[1]=h0.y; hh[2]=h0.z; hh[3]=h0.w;
    hh[4]=h1.x; hh[5]=h1.y; hh[6]=h1.z; hh[7]=h1.w;
    hh[8]=h2.x; hh[9]=h2.y; hh[10]=h2.z; hh[11]=h2.w;
    hh[12]=h3.x; hh[13]=h3.y; hh[14]=h3.z; hh[15]=h3.w;
    float ss = sbo;
    #pragma unroll
    for (int c = 0; c < 16; c++) {
        float hn = fmaf(mask, u[c], hh[c]);
        ss = fmaf(sWo[c], hn, ss);
    }
    g_outlow[idx] = 1.f / (1.f + expf(-ss));
}

// ---------- bilinear 64 -> 256 ----------
__global__ void upk(float* __restrict__ out)
{
    int idx = blockIdx.x * 256 + threadIdx.x;
    int b = idx >> 16, oy = (idx >> 8) & 255, ox = idx & 255;
    float sy = (oy + 0.5f) * 0.25f - 0.5f;
    float sx = (ox + 0.5f) * 0.25f - 0.5f;
    int y0 = (int)floorf(sy); float fy = sy - (float)y0;
    int x0 = (int)floorf(sx); float fx = sx - (float)x0;
    float wy0 = 1.f - fy, wy1 = fy; int y1 = y0 + 1;
    float wx0 = 1.f - fx, wx1 = fx; int x1 = x0 + 1;
    if (y0 < 0)  { wy0 = 0.f; y0 = 0; }
    if (y1 > 63) { wy1 = 0.f; y1 = 63; }
    if (x0 < 0)  { wx0 = 0.f; x0 = 0; }
    if (x1 > 63) { wx1 = 0.f; x1 = 63; }
    const float* src = g_outlow + b * 4096;
    float v = wy0 * (wx0 * src[y0*64 + x0] + wx1 * src[y0*64 + x1])
            + wy1 * (wx0 * src[y1*64 + x0] + wx1 * src[y1*64 + x1]);
    out[idx] = v / ((wy0 + wy1) * (wx0 + wx1));
}

extern "C" void kernel_launch(void* const* d_in, const int* in_sizes, int n_in,
                              void* d_out, int out_size)
{
    (void)in_sizes; (void)n_in; (void)out_size;
    const float* x    = (const float*)d_in[0];
    const float* fire = (const float*)d_in[1];
    const float* W1   = (const float*)d_in[2];
    const float* b1   = (const float*)d_in[3];
    const float* g1   = (const float*)d_in[4];
    const float* be1  = (const float*)d_in[5];
    const float* m1   = (const float*)d_in[6];
    const float* v1   = (const float*)d_in[7];
    const float* W2   = (const float*)d_in[8];
    const float* b2   = (const float*)d_in[9];
    const float* g2   = (const float*)d_in[10];
    const float* be2  = (const float*)d_in[11];
    const float* m2   = (const float*)d_in[12];
    const float* v2   = (const float*)d_in[13];
    const float* Wg   = (const float*)d_in[14];
    const float* a_src= (const float*)d_in[15];
    const float* a_dst= (const float*)d_in[16];
    const float* bg   = (const float*)d_in[17];
    const float* Wu1  = (const float*)d_in[18];
    const float* bu1  = (const float*)d_in[19];
    const float* Wu2  = (const float*)d_in[20];
    const float* bu2  = (const float*)d_in[21];
    const float* Wo   = (const float*)d_in[22];
    const float* bo   = (const float*)d_in[23];
    float* out = (float*)d_out;

    downconv1k<<<dim3(16, NB), 256>>>(x, W1, b1, g1, be1, m1, v1);
    conv2k<<<dim3(16, 4, NB), 256>>>(W2, b2, g2, be2, m2, v2);
    featk<<<128, 256>>>(Wg, a_src, a_dst);
    knnk<<<dim3(16, NB), 256>>>(bg);
    updk<<<128, 256>>>(fire, Wu1, bu1, Wu2, bu2, Wo, bo);
    upk<<<2048, 256>>>(out);
}

// round 16
// speedup vs baseline: 1.8545x; 1.0241x over previous
#include <cuda_runtime.h>
#include <math.h>

#define NB   8
#define NN   4096
#define HID  16

__device__ __align__(16) float g_h1[NB*64*NN];
__device__ __align__(16) float g_nodes[NB*NN*HID];
__device__ __align__(16) float g_sq[NB*NN];          // 0.5*|node|^2
__device__ __align__(16) float g_xp[NB*NN*HID];
__device__ __align__(16) float g_asr[NB*NN*4];
__device__ __align__(16) float g_adt[NB*NN*4];
__device__ __align__(16) float g_p[NB*NN*HID];
__device__ __align__(16) float g_outlow[NB*NN];

__device__ __forceinline__ unsigned long long ffma2(unsigned long long a,
                                                    unsigned long long b,
                                                    unsigned long long c) {
    unsigned long long d;
    asm("fma.rn.f32x2 %0, %1, %2, %3;" : "=l"(d) : "l"(a), "l"(b), "l"(c));
    return d;
}
__device__ __forceinline__ unsigned long long pk2(float lo, float hi) {
    unsigned long long u;
    asm("mov.b64 %0, {%1, %2};" : "=l"(u) : "r"(__float_as_uint(lo)), "r"(__float_as_uint(hi)));
    return u;
}
__device__ __forceinline__ void unpk(unsigned long long u, float& a, float& b) {
    asm("mov.b64 {%0, %1}, %2;" : "=f"(a), "=f"(b) : "l"(u));
}

// ---------- fused bilinear 256->64 + conv1 + BN + ReLU ----------
__global__ void __launch_bounds__(256) downconv1k(
    const float* __restrict__ x,
    const float* __restrict__ W1, const float* __restrict__ b1,
    const float* __restrict__ g1, const float* __restrict__ be1,
    const float* __restrict__ m1, const float* __restrict__ v1)
{
    __shared__ __align__(16) float sw[576];
    __shared__ __align__(16) float sb[64];
    __shared__ float sa[64];
    __shared__ float sxl[324];
    int t = threadIdx.x;
    int b = blockIdx.y;
    int y0 = (blockIdx.x >> 2) * 16, x0 = (blockIdx.x & 3) * 16;
    if (t < 64) {
        float a = g1[t] / sqrtf(v1[t] + 1e-5f);
        sa[t] = a;
        sb[t] = (b1[t] - m1[t]) * a + be1[t];
    }
    __syncthreads();
    for (int i = t; i < 576; i += 256) {
        int oc = i & 63, tp = i >> 6;
        sw[i] = W1[oc*9 + tp] * sa[oc];
    }
    const float* src = x + (size_t)b * 65536;
    for (int i = t; i < 324; i += 256) {
        int rr = i / 18, cc = i - rr*18;
        int oy = y0 + rr - 1, ox = x0 + cc - 1;
        float val = 0.f;
        if (oy >= 0 && oy < 64 && ox >= 0 && ox < 64) {
            float wy[8], wx[8]; float sy = 0.f, sx = 0.f;
            #pragma unroll
            for (int d = 0; d < 8; d++) {
                float w = 1.f - 0.25f * fabsf((float)d - 3.5f);
                int jy = 4*oy + d - 2, jx = 4*ox + d - 2;
                wy[d] = (jy >= 0 && jy < 256) ? w : 0.f; sy += wy[d];
                wx[d] = (jx >= 0 && jx < 256) ? w : 0.f; sx += wx[d];
            }
            float acc = 0.f;
            #pragma unroll
            for (int dy = 0; dy < 8; dy++) {
                int jy = 4*oy + dy - 2; jy = jy < 0 ? 0 : (jy > 255 ? 255 : jy);
                float ra = 0.f;
                #pragma unroll
                for (int dx = 0; dx < 8; dx++) {
                    int jx = 4*ox + dx - 2; jx = jx < 0 ? 0 : (jx > 255 ? 255 : jx);
                    ra = fmaf(wx[dx], src[jy*256 + jx], ra);
                }
                acc = fmaf(wy[dy], ra, acc);
            }
            val = acc / (sy * sx);
        }
        sxl[i] = val;
    }
    __syncthreads();
    int ty = t >> 4, tx = t & 15;
    float vin[9];
    #pragma unroll
    for (int dy = 0; dy < 3; dy++)
        #pragma unroll
        for (int dx = 0; dx < 3; dx++)
            vin[dy*3+dx] = sxl[(ty+dy)*18 + (tx+dx)];
    int y = y0 + ty, xx = x0 + tx;
    const float4* sw4 = (const float4*)sw;
    const float4* sb4 = (const float4*)sb;
    size_t base = ((size_t)b*64)*4096 + y*64 + xx;
    #pragma unroll
    for (int o4 = 0; o4 < 16; o4++) {
        float4 a = sb4[o4];
        #pragma unroll
        for (int tp = 0; tp < 9; tp++) {
            float v = vin[tp];
            float4 wv = sw4[tp*16 + o4];
            a.x = fmaf(v, wv.x, a.x); a.y = fmaf(v, wv.y, a.y);
            a.z = fmaf(v, wv.z, a.z); a.w = fmaf(v, wv.w, a.w);
        }
        g_h1[base + (size_t)(o4*4    )*4096] = fmaxf(a.x, 0.f);
        g_h1[base + (size_t)(o4*4 + 1)*4096] = fmaxf(a.y, 0.f);
        g_h1[base + (size_t)(o4*4 + 2)*4096] = fmaxf(a.z, 0.f);
        g_h1[base + (size_t)(o4*4 + 3)*4096] = fmaxf(a.w, 0.f);
    }
}

// ---------- conv2 64->16, 16x16 tile, 4 oc per block ----------
__global__ void __launch_bounds__(256) conv2k(
    const float* __restrict__ W2, const float* __restrict__ b2,
    const float* __restrict__ g2, const float* __restrict__ be2,
    const float* __restrict__ m2, const float* __restrict__ v2)
{
    __shared__ __align__(16) float swt[2304];
    __shared__ __align__(16) float tile[16*324];
    __shared__ float sA[16];
    __shared__ float sbeta[4];
    int t = threadIdx.x;
    int tilei = blockIdx.x, oq = blockIdx.y, b = blockIdx.z;
    int y0 = (tilei >> 2) * 16, x0 = (tilei & 3) * 16;
    if (t < 16) sA[t] = g2[t] / sqrtf(v2[t] + 1e-5f);
    __syncthreads();
    if (t < 4) {
        int oc = oq*4 + t;
        sbeta[t] = (b2[oc] - m2[oc]) * sA[oc] + be2[oc];
    }
    for (int e = t; e < 2304; e += 256) {
        int o = e & 3; int r = e >> 2; int tp = r % 9; int ci = r / 9;
        int oc = oq*4 + o;
        swt[e] = W2[(oc*64 + ci)*9 + tp] * sA[oc];
    }
    int ty = t >> 4, tx = t & 15;
    float a0 = 0.f, a1 = 0.f, a2 = 0.f, a3 = 0.f;
    for (int cc = 0; cc < 4; cc++) {
        __syncthreads();
        for (int i = t; i < 5184; i += 256) {
            int cl = i / 324; int rem = i - cl*324; int rr = rem / 18; int c = rem - rr*18;
            int yy = y0 + rr - 1, xc = x0 + c - 1;
            float v = 0.f;
            if (yy >= 0 && yy < 64 && xc >= 0 && xc < 64)
                v = g_h1[(((size_t)b*64 + (cc*16 + cl))*64 + yy)*64 + xc];
            tile[i] = v;
        }
        __syncthreads();
        #pragma unroll
        for (int cl = 0; cl < 16; cl++) {
            int ci = cc*16 + cl;
            float v[9];
            #pragma unroll
            for (int dy = 0; dy < 3; dy++)
                #pragma unroll
                for (int dx = 0; dx < 3; dx++)
                    v[dy*3+dx] = tile[cl*324 + (ty+dy)*18 + (tx+dx)];
            const float4* w4 = (const float4*)&swt[ci*36];
            #pragma unroll
            for (int tp = 0; tp < 9; tp++) {
                float vv = v[tp];
                float4 w = w4[tp];
                a0 = fmaf(vv, w.x, a0); a1 = fmaf(vv, w.y, a1);
                a2 = fmaf(vv, w.z, a2); a3 = fmaf(vv, w.w, a3);
            }
        }
    }
    a0 = fmaxf(a0 + sbeta[0], 0.f);
    a1 = fmaxf(a1 + sbeta[1], 0.f);
    a2 = fmaxf(a2 + sbeta[2], 0.f);
    a3 = fmaxf(a3 + sbeta[3], 0.f);
    int n = (y0 + ty)*64 + (x0 + tx);
    float4* dst = (float4*)&g_nodes[((size_t)b*NN + n)*16 + oq*4];
    dst[0] = make_float4(a0, a1, a2, a3);
}

// ---------- GAT transform + 0.5|n|^2 ----------
__global__ void featk(const float* __restrict__ Wg, const float* __restrict__ a_src,
                      const float* __restrict__ a_dst)
{
    __shared__ float sWg[256];
    __shared__ float ssrc[16], sdst[16];
    int t = threadIdx.x;
    sWg[t] = Wg[t];
    if (t < 16) { ssrc[t] = a_src[t]; sdst[t] = a_dst[t]; }
    __syncthreads();
    int idx = blockIdx.x * 256 + t;
    const float4* np = (const float4*)&g_nodes[(size_t)idx*16];
    float n[16];
    float4 v0 = np[0], v1 = np[1], v2 = np[2], v3 = np[3];
    n[0]=v0.x; n[1]=v0.y; n[2]=v0.z; n[3]=v0.w;
    n[4]=v1.x; n[5]=v1.y; n[6]=v1.z; n[7]=v1.w;
    n[8]=v2.x; n[9]=v2.y; n[10]=v2.z; n[11]=v2.w;
    n[12]=v3.x; n[13]=v3.y; n[14]=v3.z; n[15]=v3.w;
    float s = 0.f;
    #pragma unroll
    for (int c = 0; c < 16; c++) s = fmaf(n[c], n[c], s);
    g_sq[idx] = 0.5f * s;
    float xo[16];
    #pragma unroll
    for (int o = 0; o < 16; o++) {
        float a = 0.f;
        #pragma unroll
        for (int c = 0; c < 16; c++) a = fmaf(n[c], sWg[o*16 + c], a);
        xo[o] = a;
    }
    float4* xpd = (float4*)&g_xp[(size_t)idx*16];
    xpd[0] = make_float4(xo[0],xo[1],xo[2],xo[3]);
    xpd[1] = make_float4(xo[4],xo[5],xo[6],xo[7]);
    xpd[2] = make_float4(xo[8],xo[9],xo[10],xo[11]);
    xpd[3] = make_float4(xo[12],xo[13],xo[14],xo[15]);
    float av0=0,av1=0,av2=0,av3=0,dv0=0,dv1=0,dv2=0,dv3=0;
    #pragma unroll
    for (int c = 0; c < 4; c++) {
        av0 = fmaf(xo[c],    ssrc[c],    av0); dv0 = fmaf(xo[c],    sdst[c],    dv0);
        av1 = fmaf(xo[4+c],  ssrc[4+c],  av1); dv1 = fmaf(xo[4+c],  sdst[4+c],  dv1);
        av2 = fmaf(xo[8+c],  ssrc[8+c],  av2); dv2 = fmaf(xo[8+c],  sdst[8+c],  dv2);
        av3 = fmaf(xo[12+c], ssrc[12+c], av3); dv3 = fmaf(xo[12+c], sdst[12+c], dv3);
    }
    ((float4*)g_asr)[idx] = make_float4(av0,av1,av2,av3);
    ((float4*)g_adt)[idx] = make_float4(dv0,dv1,dv2,dv3);
}

// ---------- kNN top-8 + GAT: 128 rows x 2 splits, tau-seeded strict gate ----------
__global__ void __launch_bounds__(256) knnk(const float* __restrict__ bg)
{
    __shared__ __align__(16) float4 scand[2*512];   // 16 KB: [split][cand j][q]
    __shared__ float ssq[2*128];
    int t = threadIdx.x;
    int b = blockIdx.y;
    int s = t >> 7;                 // candidate split 0..1 (2048 cands each)
    int rp = t & 127;
    int row = blockIdx.x * 128 + rp;
    const float* nbase = g_nodes + (size_t)b*NN*16;
    const float* sqb = g_sq + (size_t)b*NN;

    float nv[16];
    {
        const float4* rpp = (const float4*)(nbase + (size_t)row*16);
        float4 f0 = rpp[0], f1 = rpp[1], f2 = rpp[2], f3 = rpp[3];
        nv[0]=-f0.x; nv[1]=-f0.y; nv[2]=-f0.z; nv[3]=-f0.w;
        nv[4]=-f1.x; nv[5]=-f1.y; nv[6]=-f1.z; nv[7]=-f1.w;
        nv[8]=-f2.x; nv[9]=-f2.y; nv[10]=-f2.z; nv[11]=-f2.w;
        nv[12]=-f3.x; nv[13]=-f3.y; nv[14]=-f3.z; nv[15]=-f3.w;
    }

    // tau pre-pass (per thread, redundantly per split): 8th-smallest over 24
    // spatial nbrs (5x5), packed-equivalent accE/accO rounding -> exact bound.
    float tau;
    {
        float td[8];
        #pragma unroll
        for (int p = 0; p < 8; p++) td[p] = 3e38f;
        int y = row >> 6, x = row & 63;
        int sy = y - 2; sy = sy < 0 ? 0 : (sy > 59 ? 59 : sy);
        int sx = x - 2; sx = sx < 0 ? 0 : (sx > 59 ? 59 : sx);
        for (int dy = 0; dy < 5; dy++) {
            for (int dx = 0; dx < 5; dx++) {
                int n = (sy+dy)*64 + (sx+dx);
                if (n == row) continue;
                const float4* cp4 = (const float4*)(nbase + (size_t)n*16);
                float4 c0 = cp4[0], c1 = cp4[1], c2 = cp4[2], c3 = cp4[3];
                float aE = sqb[n], aO = 0.f;
                aE = fmaf(nv[0],  c0.x, aE); aO = fmaf(nv[1],  c0.y, aO);
                aE = fmaf(nv[2],  c0.z, aE); aO = fmaf(nv[3],  c0.w, aO);
                aE = fmaf(nv[4],  c1.x, aE); aO = fmaf(nv[5],  c1.y, aO);
                aE = fmaf(nv[6],  c1.z, aE); aO = fmaf(nv[7],  c1.w, aO);
                aE = fmaf(nv[8],  c2.x, aE); aO = fmaf(nv[9],  c2.y, aO);
                aE = fmaf(nv[10], c2.z, aE); aO = fmaf(nv[11], c2.w, aO);
                aE = fmaf(nv[12], c3.x, aE); aO = fmaf(nv[13], c3.y, aO);
                aE = fmaf(nv[14], c3.z, aE); aO = fmaf(nv[15], c3.w, aO);
                float acc = aE + aO;
                if (acc < td[7]) {
                    td[7] = acc;
                    #pragma unroll
                    for (int p = 7; p > 0; p--)
                        if (td[p] < td[p-1]) { float tmp = td[p]; td[p] = td[p-1]; td[p-1] = tmp; }
                }
            }
        }
        tau = td[7];
    }
    float gate0 = nextafterf(tau, 3.4e38f);     // acc < gate0 <=> acc <= tau
    float gate = gate0;

    unsigned long long rneg[8];
    #pragma unroll
    for (int q = 0; q < 8; q++) rneg[q] = pk2(nv[2*q], nv[2*q+1]);

    // seed lists: inserts only for strict sub-tau candidates; fakes sort last
    float bd[8]; int bi[8];
    #pragma unroll
    for (int p = 0; p < 8; p++) { bd[p] = gate0; bi[p] = 0x3fffffff; }

    for (int u = 0; u < 16; u++) {
        __syncthreads();
        {
            int cb0 = s*2048 + u*128;
            const float4* src = (const float4*)nbase + (size_t)cb0*4;
            #pragma unroll
            for (int e = 0; e < 4; e++)
                scand[s*512 + e*128 + rp] = src[e*128 + rp];
            ssq[s*128 + rp] = sqb[cb0 + rp];
        }
        __syncthreads();
        int cb = s*2048 + u*128;
        const ulonglong2* fb = (const ulonglong2*)(scand + s*512);
        const float* sq_s = ssq + s*128;
        #pragma unroll 4
        for (int j = 0; j < 128; j++) {
            ulonglong2 w0 = fb[j*4+0], w1 = fb[j*4+1], w2 = fb[j*4+2], w3 = fb[j*4+3];
            unsigned long long acc = pk2(sq_s[j], 0.f);
            acc = ffma2(rneg[0], w0.x, acc); acc = ffma2(rneg[1], w0.y, acc);
            acc = ffma2(rneg[2], w1.x, acc); acc = ffma2(rneg[3], w1.y, acc);
            acc = ffma2(rneg[4], w2.x, acc); acc = ffma2(rneg[5], w2.y, acc);
            acc = ffma2(rneg[6], w3.x, acc); acc = ffma2(rneg[7], w3.y, acc);
            float lo, hi; unpk(acc, lo, hi);
            float d = lo + hi;
            if (d < gate) {                 // strict: ties rejected
                int jj = cb + j;
                if (jj != row) {
                    bd[7] = d; bi[7] = jj;
                    #pragma unroll
                    for (int p = 7; p > 0; p--)
                        if (bd[p] < bd[p-1]) {
                            float tmp = bd[p]; bd[p] = bd[p-1]; bd[p-1] = tmp;
                            int ti = bi[p]; bi[p] = bi[p-1]; bi[p-1] = ti;
                        }
                    gate = bd[7];
                }
            }
        }
    }

    // per-split lists [s][p][rp] (alias tile region: 2048 floats + 2048 ints)
    __syncthreads();
    float* md = (float*)scand;
    int*   mi = (int*)(scand + 512);
    #pragma unroll
    for (int p = 0; p < 8; p++) {
        md[(s*8 + p)*128 + rp] = bd[p];
        mi[(s*8 + p)*128 + rp] = bi[p];
    }
    __syncthreads();
    if (t >= 128) return;

    // 2-way merge (tie -> split 0 = lower index)
    int ptr0 = 0, ptr1 = 0;
    int nb[8];
    #pragma unroll
    for (int k = 0; k < 8; k++) {
        float d0 = md[ptr0*128 + t];
        float d1 = md[(8 + ptr1)*128 + t];
        if (d1 < d0) { nb[k] = mi[(8 + ptr1)*128 + t]; ptr1++; }
        else         { nb[k] = mi[ptr0*128 + t];       ptr0++; }
    }

    // GAT aggregation over 8 neighbors + self
    int row2 = blockIdx.x * 128 + t;
    float4 adv = ((const float4*)g_adt)[b*NN + row2];
    float ad0 = adv.x, ad1 = adv.y, ad2 = adv.z, ad3 = adv.w;
    int idxs[9];
    #pragma unroll
    for (int k = 0; k < 8; k++) idxs[k] = nb[k];
    idxs[8] = row2;
    float lg[36];
    float m0 = -3e38f, m1 = -3e38f, m2 = -3e38f, m3 = -3e38f;
    #pragma unroll
    for (int k = 0; k < 9; k++) {
        float4 av = ((const float4*)g_asr)[b*NN + idxs[k]];
        float l0 = av.x + ad0; l0 = l0 > 0.f ? l0 : 0.2f*l0;
        float l1 = av.y + ad1; l1 = l1 > 0.f ? l1 : 0.2f*l1;
        float l2 = av.z + ad2; l2 = l2 > 0.f ? l2 : 0.2f*l2;
        float l3 = av.w + ad3; l3 = l3 > 0.f ? l3 : 0.2f*l3;
        lg[k*4+0] = l0; lg[k*4+1] = l1; lg[k*4+2] = l2; lg[k*4+3] = l3;
        m0 = fmaxf(m0, l0); m1 = fmaxf(m1, l1); m2 = fmaxf(m2, l2); m3 = fmaxf(m3, l3);
    }
    float s0 = 0.f, s1 = 0.f, s2 = 0.f, s3 = 0.f;
    float out[16];
    #pragma unroll
    for (int c = 0; c < 16; c++) out[c] = 0.f;
    #pragma unroll
    for (int k = 0; k < 9; k++) {
        float w0 = expf(lg[k*4+0] - m0);
        float w1 = expf(lg[k*4+1] - m1);
        float w2 = expf(lg[k*4+2] - m2);
        float w3 = expf(lg[k*4+3] - m3);
        s0 += w0; s1 += w1; s2 += w2; s3 += w3;
        const float4* xp4 = (const float4*)g_xp + ((size_t)b*NN + idxs[k])*4;
        float4 x0 = xp4[0], x1 = xp4[1], x2 = xp4[2], x3 = xp4[3];
        out[0]  = fmaf(w0, x0.x, out[0]);  out[1]  = fmaf(w0, x0.y, out[1]);
        out[2]  = fmaf(w0, x0.z, out[2]);  out[3]  = fmaf(w0, x0.w, out[3]);
        out[4]  = fmaf(w1, x1.x, out[4]);  out[5]  = fmaf(w1, x1.y, out[5]);
        out[6]  = fmaf(w1, x1.z, out[6]);  out[7]  = fmaf(w1, x1.w, out[7]);
        out[8]  = fmaf(w2, x2.x, out[8]);  out[9]  = fmaf(w2, x2.y, out[9]);
        out[10] = fmaf(w2, x2.z, out[10]); out[11] = fmaf(w2, x2.w, out[11]);
        out[12] = fmaf(w3, x3.x, out[12]); out[13] = fmaf(w3, x3.y, out[13]);
        out[14] = fmaf(w3, x3.z, out[14]); out[15] = fmaf(w3, x3.w, out[15]);
    }
    float inv0 = 1.f/s0, inv1 = 1.f/s1, inv2 = 1.f/s2, inv3 = 1.f/s3;
    float res[16];
    #pragma unroll
    for (int c = 0; c < 4;  c++) res[c] = fmaxf(out[c]*inv0 + bg[c], 0.f);
    #pragma unroll
    for (int c = 4; c < 8;  c++) res[c] = fmaxf(out[c]*inv1 + bg[c], 0.f);
    #pragma unroll
    for (int c = 8; c < 12; c++) res[c] = fmaxf(out[c]*inv2 + bg[c], 0.f);
    #pragma unroll
    for (int c = 12; c < 16; c++) res[c] = fmaxf(out[c]*inv3 + bg[c], 0.f);
    float4* pd = (float4*)g_p + ((size_t)b*NN + row2)*4;
    pd[0] = make_float4(res[0],res[1],res[2],res[3]);
    pd[1] = make_float4(res[4],res[5],res[6],res[7]);
    pd[2] = make_float4(res[8],res[9],res[10],res[11]);
    pd[3] = make_float4(res[12],res[13],res[14],res[15]);
}

// ---------- update MLP + fire + out conv + sigmoid ----------
__global__ void updk(const float* __restrict__ fire, const float* __restrict__ Wu1,
                     const float* __restrict__ bu1, const float* __restrict__ Wu2,
                     const float* __restrict__ bu2,
                     const float* __restrict__ Wo,  const float* __restrict__ bo)
{
    __shared__ __align__(16) float sW1[2048];
    __shared__ __align__(16) float sW2[2048];
    __shared__ float sb1[128], sb2[16], sWo[16];
    __shared__ float sbo;
    int t = threadIdx.x;
    for (int i = t; i < 2048; i += 256) {
        sW1[i] = Wu1[i];
        int h = i >> 4, o = i & 15;
        sW2[i] = Wu2[o*128 + h];
    }
    if (t < 128) sb1[t] = bu1[t];
    if (t < 16)  { sb2[t] = bu2[t]; sWo[t] = Wo[t]; }
    if (t == 0)  sbo = bo[0];
    __syncthreads();
    int idx = blockIdx.x * 256 + t;
    const float4* pp = (const float4*)(g_p + (size_t)idx*16);
    float4 p0 = pp[0], p1 = pp[1], p2 = pp[2], p3 = pp[3];
    float p[16];
    p[0]=p0.x; p[1]=p0.y; p[2]=p0.z; p[3]=p0.w;
    p[4]=p1.x; p[5]=p1.y; p[6]=p1.z; p[7]=p1.w;
    p[8]=p2.x; p[9]=p2.y; p[10]=p2.z; p[11]=p2.w;
    p[12]=p3.x; p[13]=p3.y; p[14]=p3.z; p[15]=p3.w;
    float u[16];
    #pragma unroll
    for (int o = 0; o < 16; o++) u[o] = sb2[o];
    #pragma unroll 2
    for (int h = 0; h < 128; h++) {
        float a = sb1[h];
        const float4* w1p = (const float4*)&sW1[h*16];
        float4 wa = w1p[0], wb = w1p[1], wc = w1p[2], wd = w1p[3];
        a = fmaf(p[0],wa.x,a); a = fmaf(p[1],wa.y,a); a = fmaf(p[2],wa.z,a); a = fmaf(p[3],wa.w,a);
        a = fmaf(p[4],wb.x,a); a = fmaf(p[5],wb.y,a); a = fmaf(p[6],wb.z,a); a = fmaf(p[7],wb.w,a);
        a = fmaf(p[8],wc.x,a); a = fmaf(p[9],wc.y,a); a = fmaf(p[10],wc.z,a); a = fmaf(p[11],wc.w,a);
        a = fmaf(p[12],wd.x,a); a = fmaf(p[13],wd.y,a); a = fmaf(p[14],wd.z,a); a = fmaf(p[15],wd.w,a);
        a = fmaxf(a, 0.f);
        const float4* w2p = (const float4*)&sW2[h*16];
        float4 va = w2p[0], vb = w2p[1], vc = w2p[2], vd = w2p[3];
        u[0]  = fmaf(a,va.x,u[0]);  u[1]  = fmaf(a,va.y,u[1]);
        u[2]  = fmaf(a,va.z,u[2]);  u[3]  = fmaf(a,va.w,u[3]);
        u[4]  = fmaf(a,vb.x,u[4]);  u[5]  = fmaf(a,vb.y,u[5]);
        u[6]  = fmaf(a,vb.z,u[6]);  u[7]  = fmaf(a,vb.w,u[7]);
        u[8]  = fmaf(a,vc.x,u[8]);  u[9]  = fmaf(a,vc.y,u[9]);
        u[10] = fmaf(a,vc.z,u[10]); u[11] = fmaf(a,vc.w,u[11]);
        u[12] = fmaf(a,vd.x,u[12]); u[13] = fmaf(a,vd.y,u[13]);
        u[14] = fmaf(a,vd.z,u[14]); u[15] = fmaf(a,vd.w,u[15]);
    }
    float mask = fire[idx] < 0.5f ? 1.f : 0.f;
    const float4* hp = (const float4*)(g_nodes + (size_t)idx*16);
    float4 h0 = hp[0], h1 = hp[1], h2 = hp[2], h3 = hp[3];
    float hh[16];
    hh[0]=h0.x; hh[1]=h0.y; hh[2]=h0.z; hh[3]=h0.w;
    hh[4]=h1.x; hh[5]=h1.y; hh[6]=h1.z; hh[7]=h1.w;
    hh[8]=h2.x; hh[9]=h2.y; hh[10]=h2.z; hh[11]=h2.w;
    hh[12]=h3.x; hh[13]=h3.y; hh[14]=h3.z; hh[15]=h3.w;
    float ss = sbo;
    #pragma unroll
    for (int c = 0; c < 16; c++) {
        float hn = fmaf(mask, u[c], hh[c]);
        ss = fmaf(sWo[c], hn, ss);
    }
    g_outlow[idx] = 1.f / (1.f + expf(-ss));
}

// ---------- bilinear 64 -> 256 ----------
__global__ void upk(float* __restrict__ out)
{
    int idx = blockIdx.x * 256 + threadIdx.x;
    int b = idx >> 16, oy = (idx >> 8) & 255, ox = idx & 255;
    float sy = (oy + 0.5f) * 0.25f - 0.5f;
    float sx = (ox + 0.5f) * 0.25f - 0.5f;
    int y0 = (int)floorf(sy); float fy = sy - (float)y0;
    int x0 = (int)floorf(sx); float fx = sx - (float)x0;
    float wy0 = 1.f - fy, wy1 = fy; int y1 = y0 + 1;
    float wx0 = 1.f - fx, wx1 = fx; int x1 = x0 + 1;
    if (y0 < 0)  { wy0 = 0.f; y0 = 0; }
    if (y1 > 63) { wy1 = 0.f; y1 = 63; }
    if (x0 < 0)  { wx0 = 0.f; x0 = 0; }
    if (x1 > 63) { wx1 = 0.f; x1 = 63; }
    const float* src = g_outlow + b * 4096;
    float v = wy0 * (wx0 * src[y0*64 + x0] + wx1 * src[y0*64 + x1])
            + wy1 * (wx0 * src[y1*64 + x0] + wx1 * src[y1*64 + x1]);
    out[idx] = v / ((wy0 + wy1) * (wx0 + wx1));
}

extern "C" void kernel_launch(void* const* d_in, const int* in_sizes, int n_in,
                              void* d_out, int out_size)
{
    (void)in_sizes; (void)n_in; (void)out_size;
    const float* x    = (const float*)d_in[0];
    const float* fire = (const float*)d_in[1];
    const float* W1   = (const float*)d_in[2];
    const float* b1   = (const float*)d_in[3];
    const float* g1   = (const float*)d_in[4];
    const float* be1  = (const float*)d_in[5];
    const float* m1   = (const float*)d_in[6];
    const float* v1   = (const float*)d_in[7];
    const float* W2   = (const float*)d_in[8];
    const float* b2   = (const float*)d_in[9];
    const float* g2   = (const float*)d_in[10];
    const float* be2  = (const float*)d_in[11];
    const float* m2   = (const float*)d_in[12];
    const float* v2   = (const float*)d_in[13];
    const float* Wg   = (const float*)d_in[14];
    const float* a_src= (const float*)d_in[15];
    const float* a_dst= (const float*)d_in[16];
    const float* bg   = (const float*)d_in[17];
    const float* Wu1  = (const float*)d_in[18];
    const float* bu1  = (const float*)d_in[19];
    const float* Wu2  = (const float*)d_in[20];
    const float* bu2  = (const float*)d_in[21];
    const float* Wo   = (const float*)d_in[22];
    const float* bo   = (const float*)d_in[23];
    float* out = (float*)d_out;

    downconv1k<<<dim3(16, NB), 256>>>(x, W1, b1, g1, be1, m1, v1);
    conv2k<<<dim3(16, 4, NB), 256>>>(W2, b2, g2, be2, m2, v2);
    featk<<<128, 256>>>(Wg, a_src, a_dst);
    knnk<<<dim3(32, NB), 256>>>(bg);
    updk<<<128, 256>>>(fire, Wu1, bu1, Wu2, bu2, Wo, bo);
    upk<<<2048, 256>>>(out);
}

// round 17
// speedup vs baseline: 2.4243x; 1.3072x over previous
#include <cuda_runtime.h>
#include <math.h>

#define NB   8
#define NN   4096
#define HID  16

__device__ __align__(16) float g_h1[NB*64*NN];
__device__ __align__(16) float g_nodes[NB*NN*HID];
__device__ __align__(16) float g_sq[NB*NN];          // 0.5*|node|^2
__device__ __align__(16) float g_xp[NB*NN*HID];
__device__ __align__(16) float g_asr[NB*NN*4];
__device__ __align__(16) float g_adt[NB*NN*4];
__device__ __align__(16) float g_p[NB*NN*HID];
__device__ __align__(16) float g_outlow[NB*NN];

__device__ __forceinline__ unsigned long long ffma2(unsigned long long a,
                                                    unsigned long long b,
                                                    unsigned long long c) {
    unsigned long long d;
    asm("fma.rn.f32x2 %0, %1, %2, %3;" : "=l"(d) : "l"(a), "l"(b), "l"(c));
    return d;
}
__device__ __forceinline__ unsigned long long pk2(float lo, float hi) {
    unsigned long long u;
    asm("mov.b64 %0, {%1, %2};" : "=l"(u) : "r"(__float_as_uint(lo)), "r"(__float_as_uint(hi)));
    return u;
}
__device__ __forceinline__ void unpk(unsigned long long u, float& a, float& b) {
    asm("mov.b64 {%0, %1}, %2;" : "=f"(a), "=f"(b) : "l"(u));
}

// ---------- fused bilinear 256->64 + conv1 + BN + ReLU ----------
__global__ void __launch_bounds__(256) downconv1k(
    const float* __restrict__ x,
    const float* __restrict__ W1, const float* __restrict__ b1,
    const float* __restrict__ g1, const float* __restrict__ be1,
    const float* __restrict__ m1, const float* __restrict__ v1)
{
    __shared__ __align__(16) float sw[576];
    __shared__ __align__(16) float sb[64];
    __shared__ float sa[64];
    __shared__ float sxl[324];
    int t = threadIdx.x;
    int b = blockIdx.y;
    int y0 = (blockIdx.x >> 2) * 16, x0 = (blockIdx.x & 3) * 16;
    if (t < 64) {
        float a = g1[t] / sqrtf(v1[t] + 1e-5f);
        sa[t] = a;
        sb[t] = (b1[t] - m1[t]) * a + be1[t];
    }
    __syncthreads();
    for (int i = t; i < 576; i += 256) {
        int oc = i & 63, tp = i >> 6;
        sw[i] = W1[oc*9 + tp] * sa[oc];
    }
    const float* src = x + (size_t)b * 65536;
    for (int i = t; i < 324; i += 256) {
        int rr = i / 18, cc = i - rr*18;
        int oy = y0 + rr - 1, ox = x0 + cc - 1;
        float val = 0.f;
        if (oy >= 0 && oy < 64 && ox >= 0 && ox < 64) {
            float wy[8], wx[8]; float sy = 0.f, sx = 0.f;
            #pragma unroll
            for (int d = 0; d < 8; d++) {
                float w = 1.f - 0.25f * fabsf((float)d - 3.5f);
                int jy = 4*oy + d - 2, jx = 4*ox + d - 2;
                wy[d] = (jy >= 0 && jy < 256) ? w : 0.f; sy += wy[d];
                wx[d] = (jx >= 0 && jx < 256) ? w : 0.f; sx += wx[d];
            }
            float acc = 0.f;
            #pragma unroll
            for (int dy = 0; dy < 8; dy++) {
                int jy = 4*oy + dy - 2; jy = jy < 0 ? 0 : (jy > 255 ? 255 : jy);
                float ra = 0.f;
                #pragma unroll
                for (int dx = 0; dx < 8; dx++) {
                    int jx = 4*ox + dx - 2; jx = jx < 0 ? 0 : (jx > 255 ? 255 : jx);
                    ra = fmaf(wx[dx], src[jy*256 + jx], ra);
                }
                acc = fmaf(wy[dy], ra, acc);
            }
            val = acc / (sy * sx);
        }
        sxl[i] = val;
    }
    __syncthreads();
    int ty = t >> 4, tx = t & 15;
    float vin[9];
    #pragma unroll
    for (int dy = 0; dy < 3; dy++)
        #pragma unroll
        for (int dx = 0; dx < 3; dx++)
            vin[dy*3+dx] = sxl[(ty+dy)*18 + (tx+dx)];
    int y = y0 + ty, xx = x0 + tx;
    const float4* sw4 = (const float4*)sw;
    const float4* sb4 = (const float4*)sb;
    size_t base = ((size_t)b*64)*4096 + y*64 + xx;
    #pragma unroll
    for (int o4 = 0; o4 < 16; o4++) {
        float4 a = sb4[o4];
        #pragma unroll
        for (int tp = 0; tp < 9; tp++) {
            float v = vin[tp];
            float4 wv = sw4[tp*16 + o4];
            a.x = fmaf(v, wv.x, a.x); a.y = fmaf(v, wv.y, a.y);
            a.z = fmaf(v, wv.z, a.z); a.w = fmaf(v, wv.w, a.w);
        }
        g_h1[base + (size_t)(o4*4    )*4096] = fmaxf(a.x, 0.f);
        g_h1[base + (size_t)(o4*4 + 1)*4096] = fmaxf(a.y, 0.f);
        g_h1[base + (size_t)(o4*4 + 2)*4096] = fmaxf(a.z, 0.f);
        g_h1[base + (size_t)(o4*4 + 3)*4096] = fmaxf(a.w, 0.f);
    }
}

// ---------- conv2 64->16, 16x16 tile, 4 oc per block ----------
__global__ void __launch_bounds__(256) conv2k(
    const float* __restrict__ W2, const float* __restrict__ b2,
    const float* __restrict__ g2, const float* __restrict__ be2,
    const float* __restrict__ m2, const float* __restrict__ v2)
{
    __shared__ __align__(16) float swt[2304];
    __shared__ __align__(16) float tile[16*324];
    __shared__ float sA[16];
    __shared__ float sbeta[4];
    int t = threadIdx.x;
    int tilei = blockIdx.x, oq = blockIdx.y, b = blockIdx.z;
    int y0 = (tilei >> 2) * 16, x0 = (tilei & 3) * 16;
    if (t < 16) sA[t] = g2[t] / sqrtf(v2[t] + 1e-5f);
    __syncthreads();
    if (t < 4) {
        int oc = oq*4 + t;
        sbeta[t] = (b2[oc] - m2[oc]) * sA[oc] + be2[oc];
    }
    for (int e = t; e < 2304; e += 256) {
        int o = e & 3; int r = e >> 2; int tp = r % 9; int ci = r / 9;
        int oc = oq*4 + o;
        swt[e] = W2[(oc*64 + ci)*9 + tp] * sA[oc];
    }
    int ty = t >> 4, tx = t & 15;
    float a0 = 0.f, a1 = 0.f, a2 = 0.f, a3 = 0.f;
    for (int cc = 0; cc < 4; cc++) {
        __syncthreads();
        for (int i = t; i < 5184; i += 256) {
            int cl = i / 324; int rem = i - cl*324; int rr = rem / 18; int c = rem - rr*18;
            int yy = y0 + rr - 1, xc = x0 + c - 1;
            float v = 0.f;
            if (yy >= 0 && yy < 64 && xc >= 0 && xc < 64)
                v = g_h1[(((size_t)b*64 + (cc*16 + cl))*64 + yy)*64 + xc];
            tile[i] = v;
        }
        __syncthreads();
        #pragma unroll
        for (int cl = 0; cl < 16; cl++) {
            int ci = cc*16 + cl;
            float v[9];
            #pragma unroll
            for (int dy = 0; dy < 3; dy++)
                #pragma unroll
                for (int dx = 0; dx < 3; dx++)
                    v[dy*3+dx] = tile[cl*324 + (ty+dy)*18 + (tx+dx)];
            const float4* w4 = (const float4*)&swt[ci*36];
            #pragma unroll
            for (int tp = 0; tp < 9; tp++) {
                float vv = v[tp];
                float4 w = w4[tp];
                a0 = fmaf(vv, w.x, a0); a1 = fmaf(vv, w.y, a1);
                a2 = fmaf(vv, w.z, a2); a3 = fmaf(vv, w.w, a3);
            }
        }
    }
    a0 = fmaxf(a0 + sbeta[0], 0.f);
    a1 = fmaxf(a1 + sbeta[1], 0.f);
    a2 = fmaxf(a2 + sbeta[2], 0.f);
    a3 = fmaxf(a3 + sbeta[3], 0.f);
    int n = (y0 + ty)*64 + (x0 + tx);
    float4* dst = (float4*)&g_nodes[((size_t)b*NN + n)*16 + oq*4];
    dst[0] = make_float4(a0, a1, a2, a3);
}

// ---------- GAT transform + 0.5|n|^2 ----------
__global__ void featk(const float* __restrict__ Wg, const float* __restrict__ a_src,
                      const float* __restrict__ a_dst)
{
    __shared__ float sWg[256];
    __shared__ float ssrc[16], sdst[16];
    int t = threadIdx.x;
    sWg[t] = Wg[t];
    if (t < 16) { ssrc[t] = a_src[t]; sdst[t] = a_dst[t]; }
    __syncthreads();
    int idx = blockIdx.x * 256 + t;
    const float4* np = (const float4*)&g_nodes[(size_t)idx*16];
    float n[16];
    float4 v0 = np[0], v1 = np[1], v2 = np[2], v3 = np[3];
    n[0]=v0.x; n[1]=v0.y; n[2]=v0.z; n[3]=v0.w;
    n[4]=v1.x; n[5]=v1.y; n[6]=v1.z; n[7]=v1.w;
    n[8]=v2.x; n[9]=v2.y; n[10]=v2.z; n[11]=v2.w;
    n[12]=v3.x; n[13]=v3.y; n[14]=v3.z; n[15]=v3.w;
    float s = 0.f;
    #pragma unroll
    for (int c = 0; c < 16; c++) s = fmaf(n[c], n[c], s);
    g_sq[idx] = 0.5f * s;
    float xo[16];
    #pragma unroll
    for (int o = 0; o < 16; o++) {
        float a = 0.f;
        #pragma unroll
        for (int c = 0; c < 16; c++) a = fmaf(n[c], sWg[o*16 + c], a);
        xo[o] = a;
    }
    float4* xpd = (float4*)&g_xp[(size_t)idx*16];
    xpd[0] = make_float4(xo[0],xo[1],xo[2],xo[3]);
    xpd[1] = make_float4(xo[4],xo[5],xo[6],xo[7]);
    xpd[2] = make_float4(xo[8],xo[9],xo[10],xo[11]);
    xpd[3] = make_float4(xo[12],xo[13],xo[14],xo[15]);
    float av0=0,av1=0,av2=0,av3=0,dv0=0,dv1=0,dv2=0,dv3=0;
    #pragma unroll
    for (int c = 0; c < 4; c++) {
        av0 = fmaf(xo[c],    ssrc[c],    av0); dv0 = fmaf(xo[c],    sdst[c],    dv0);
        av1 = fmaf(xo[4+c],  ssrc[4+c],  av1); dv1 = fmaf(xo[4+c],  sdst[4+c],  dv1);
        av2 = fmaf(xo[8+c],  ssrc[8+c],  av2); dv2 = fmaf(xo[8+c],  sdst[8+c],  dv2);
        av3 = fmaf(xo[12+c], ssrc[12+c], av3); dv3 = fmaf(xo[12+c], sdst[12+c], dv3);
    }
    ((float4*)g_asr)[idx] = make_float4(av0,av1,av2,av3);
    ((float4*)g_adt)[idx] = make_float4(dv0,dv1,dv2,dv3);
}

// ---------- kNN top-8 + GAT: 128 rows x 2 splits, tau gate + predicated spill ----------
__global__ void __launch_bounds__(256) knnk(const float* __restrict__ bg)
{
    __shared__ __align__(16) float4 scand[2*512];   // 16 KB: [split][cand j][q]
    __shared__ float ssq[2*128];
    __shared__ __align__(8) float2 sbuf[16*256];    // 32 KB: [slot][thread]
    int t = threadIdx.x;
    int b = blockIdx.y;
    int s = t >> 7;                 // candidate split 0..1 (2048 cands each)
    int rp = t & 127;
    int row = blockIdx.x * 128 + rp;
    const float* nbase = g_nodes + (size_t)b*NN*16;
    const float* sqb = g_sq + (size_t)b*NN;

    float nv[16];
    {
        const float4* rpp = (const float4*)(nbase + (size_t)row*16);
        float4 f0 = rpp[0], f1 = rpp[1], f2 = rpp[2], f3 = rpp[3];
        nv[0]=-f0.x; nv[1]=-f0.y; nv[2]=-f0.z; nv[3]=-f0.w;
        nv[4]=-f1.x; nv[5]=-f1.y; nv[6]=-f1.z; nv[7]=-f1.w;
        nv[8]=-f2.x; nv[9]=-f2.y; nv[10]=-f2.z; nv[11]=-f2.w;
        nv[12]=-f3.x; nv[13]=-f3.y; nv[14]=-f3.z; nv[15]=-f3.w;
    }

    // tau pre-pass: 8th-smallest over 24 spatial nbrs (5x5), packed-equivalent
    // accE/accO rounding -> exact upper bound on true d8.
    float tau;
    {
        float td[8];
        #pragma unroll
        for (int p = 0; p < 8; p++) td[p] = 3e38f;
        int y = row >> 6, x = row & 63;
        int sy = y - 2; sy = sy < 0 ? 0 : (sy > 59 ? 59 : sy);
        int sx = x - 2; sx = sx < 0 ? 0 : (sx > 59 ? 59 : sx);
        for (int dy = 0; dy < 5; dy++) {
            for (int dx = 0; dx < 5; dx++) {
                int n = (sy+dy)*64 + (sx+dx);
                if (n == row) continue;
                const float4* cp4 = (const float4*)(nbase + (size_t)n*16);
                float4 c0 = cp4[0], c1 = cp4[1], c2 = cp4[2], c3 = cp4[3];
                float aE = sqb[n], aO = 0.f;
                aE = fmaf(nv[0],  c0.x, aE); aO = fmaf(nv[1],  c0.y, aO);
                aE = fmaf(nv[2],  c0.z, aE); aO = fmaf(nv[3],  c0.w, aO);
                aE = fmaf(nv[4],  c1.x, aE); aO = fmaf(nv[5],  c1.y, aO);
                aE = fmaf(nv[6],  c1.z, aE); aO = fmaf(nv[7],  c1.w, aO);
                aE = fmaf(nv[8],  c2.x, aE); aO = fmaf(nv[9],  c2.y, aO);
                aE = fmaf(nv[10], c2.z, aE); aO = fmaf(nv[11], c2.w, aO);
                aE = fmaf(nv[12], c3.x, aE); aO = fmaf(nv[13], c3.y, aO);
                aE = fmaf(nv[14], c3.z, aE); aO = fmaf(nv[15], c3.w, aO);
                float acc = aE + aO;
                if (acc < td[7]) {
                    td[7] = acc;
                    #pragma unroll
                    for (int p = 7; p > 0; p--)
                        if (td[p] < td[p-1]) { float tmp = td[p]; td[p] = td[p-1]; td[p-1] = tmp; }
                }
            }
        }
        tau = td[7];
    }
    float gate0 = nextafterf(tau, 3.4e38f);     // d < gate0 <=> d <= tau
    float gate = gate0;

    unsigned long long rneg[8];
    #pragma unroll
    for (int q = 0; q < 8; q++) rneg[q] = pk2(nv[2*q], nv[2*q+1]);

    float bd[8]; int bi[8];
    #pragma unroll
    for (int p = 0; p < 8; p++) { bd[p] = gate0; bi[p] = 0x3fffffff; }

    unsigned sbase = (unsigned)__cvta_generic_to_shared(sbuf) + t*8u;
    unsigned saddr = sbase;
    int cnt = 0;
    int jbase = 0;      // candidate indices stored relative-absolute below

    for (int u = 0; u < 16; u++) {
        __syncthreads();
        {
            int cb0 = s*2048 + u*128;
            const float4* src = (const float4*)nbase + (size_t)cb0*4;
            #pragma unroll
            for (int e = 0; e < 4; e++)
                scand[s*512 + e*128 + rp] = src[e*128 + rp];
            ssq[s*128 + rp] = sqb[cb0 + rp];
        }
        __syncthreads();
        int cb = s*2048 + u*128;
        const ulonglong2* fb = (const ulonglong2*)(scand + s*512);
        const float* sq_s = ssq + s*128;
        for (int j4 = 0; j4 < 32; j4++) {
            #pragma unroll
            for (int q4 = 0; q4 < 4; q4++) {
                int j = j4*4 + q4;
                ulonglong2 w0 = fb[j*4+0], w1 = fb[j*4+1], w2 = fb[j*4+2], w3 = fb[j*4+3];
                unsigned long long acc = pk2(sq_s[j], 0.f);
                acc = ffma2(rneg[0], w0.x, acc); acc = ffma2(rneg[1], w0.y, acc);
                acc = ffma2(rneg[2], w1.x, acc); acc = ffma2(rneg[3], w1.y, acc);
                acc = ffma2(rneg[4], w2.x, acc); acc = ffma2(rneg[5], w2.y, acc);
                acc = ffma2(rneg[6], w3.x, acc); acc = ffma2(rneg[7], w3.y, acc);
                float lo, hi; unpk(acc, lo, hi);
                float d = lo + hi;
                // predicated append (no BSSY): store (d, idx) if d < gate
                unsigned pr;
                asm volatile(
                    "{\n .reg .pred p;\n"
                    " setp.lt.f32 p, %2, %3;\n"
                    " @p st.shared.v2.f32 [%1], {%2, %4};\n"
                    " selp.u32 %0, 1, 0, p;\n}"
                    : "=r"(pr)
                    : "r"(saddr), "f"(d), "f"(gate),
                      "f"(__int_as_float(cb + j)));
                saddr += pr << 11;     // slot stride 256*8 bytes
                cnt += pr;
            }
            if (__any_sync(0xffffffffu, cnt >= 12)) {
                // collective fold: strict, index order preserved
                for (int i = 0; i < cnt; i++) {
                    float2 e = sbuf[i*256 + t];
                    int jj = __float_as_int(e.y);
                    float d = e.x;
                    if (d < bd[7] && jj != row) {
                        bd[7] = d; bi[7] = jj;
                        #pragma unroll
                        for (int p = 7; p > 0; p--)
                            if (bd[p] < bd[p-1]) {
                                float tmp = bd[p]; bd[p] = bd[p-1]; bd[p-1] = tmp;
                                int ti = bi[p]; bi[p] = bi[p-1]; bi[p-1] = ti;
                            }
                    }
                }
                cnt = 0; saddr = sbase;
                gate = bd[7];
            }
        }
    }
    // final fold
    for (int i = 0; i < cnt; i++) {
        float2 e = sbuf[i*256 + t];
        int jj = __float_as_int(e.y);
        float d = e.x;
        if (d < bd[7] && jj != row) {
            bd[7] = d; bi[7] = jj;
            #pragma unroll
            for (int p = 7; p > 0; p--)
                if (bd[p] < bd[p-1]) {
                    float tmp = bd[p]; bd[p] = bd[p-1]; bd[p-1] = tmp;
                    int ti = bi[p]; bi[p] = bi[p-1]; bi[p-1] = ti;
                }
        }
    }
    (void)jbase;

    // per-split lists [s][p][rp] (alias tile region: 2048 floats + 2048 ints)
    __syncthreads();
    float* md = (float*)scand;
    int*   mi = (int*)(scand + 512);
    #pragma unroll
    for (int p = 0; p < 8; p++) {
        md[(s*8 + p)*128 + rp] = bd[p];
        mi[(s*8 + p)*128 + rp] = bi[p];
    }
    __syncthreads();
    if (t >= 128) return;

    // 2-way merge (tie -> split 0 = lower index; fakes d=gate0 sort last)
    int ptr0 = 0, ptr1 = 0;
    int nb[8];
    #pragma unroll
    for (int k = 0; k < 8; k++) {
        float d0 = md[ptr0*128 + t];
        float d1 = md[(8 + ptr1)*128 + t];
        if (d1 < d0) { nb[k] = mi[(8 + ptr1)*128 + t]; ptr1++; }
        else         { nb[k] = mi[ptr0*128 + t];       ptr0++; }
    }

    // GAT aggregation over 8 neighbors + self
    int row2 = blockIdx.x * 128 + t;
    float4 adv = ((const float4*)g_adt)[b*NN + row2];
    float ad0 = adv.x, ad1 = adv.y, ad2 = adv.z, ad3 = adv.w;
    int idxs[9];
    #pragma unroll
    for (int k = 0; k < 8; k++) idxs[k] = nb[k];
    idxs[8] = row2;
    float lg[36];
    float m0 = -3e38f, m1 = -3e38f, m2 = -3e38f, m3 = -3e38f;
    #pragma unroll
    for (int k = 0; k < 9; k++) {
        float4 av = ((const float4*)g_asr)[b*NN + idxs[k]];
        float l0 = av.x + ad0; l0 = l0 > 0.f ? l0 : 0.2f*l0;
        float l1 = av.y + ad1; l1 = l1 > 0.f ? l1 : 0.2f*l1;
        float l2 = av.z + ad2; l2 = l2 > 0.f ? l2 : 0.2f*l2;
        float l3 = av.w + ad3; l3 = l3 > 0.f ? l3 : 0.2f*l3;
        lg[k*4+0] = l0; lg[k*4+1] = l1; lg[k*4+2] = l2; lg[k*4+3] = l3;
        m0 = fmaxf(m0, l0); m1 = fmaxf(m1, l1); m2 = fmaxf(m2, l2); m3 = fmaxf(m3, l3);
    }
    float s0 = 0.f, s1 = 0.f, s2 = 0.f, s3 = 0.f;
    float out[16];
    #pragma unroll
    for (int c = 0; c < 16; c++) out[c] = 0.f;
    #pragma unroll
    for (int k = 0; k < 9; k++) {
        float w0 = expf(lg[k*4+0] - m0);
        float w1 = expf(lg[k*4+1] - m1);
        float w2 = expf(lg[k*4+2] - m2);
        float w3 = expf(lg[k*4+3] - m3);
        s0 += w0; s1 += w1; s2 += w2; s3 += w3;
        const float4* xp4 = (const float4*)g_xp + ((size_t)b*NN + idxs[k])*4;
        float4 x0 = xp4[0], x1 = xp4[1], x2 = xp4[2], x3 = xp4[3];
        out[0]  = fmaf(w0, x0.x, out[0]);  out[1]  = fmaf(w0, x0.y, out[1]);
        out[2]  = fmaf(w0, x0.z, out[2]);  out[3]  = fmaf(w0, x0.w, out[3]);
        out[4]  = fmaf(w1, x1.x, out[4]);  out[5]  = fmaf(w1, x1.y, out[5]);
        out[6]  = fmaf(w1, x1.z, out[6]);  out[7]  = fmaf(w1, x1.w, out[7]);
        out[8]  = fmaf(w2, x2.x, out[8]);  out[9]  = fmaf(w2, x2.y, out[9]);
        out[10] = fmaf(w2, x2.z, out[10]); out[11] = fmaf(w2, x2.w, out[11]);
        out[12] = fmaf(w3, x3.x, out[12]); out[13] = fmaf(w3, x3.y, out[13]);
        out[14] = fmaf(w3, x3.z, out[14]); out[15] = fmaf(w3, x3.w, out[15]);
    }
    float inv0 = 1.f/s0, inv1 = 1.f/s1, inv2 = 1.f/s2, inv3 = 1.f/s3;
    float res[16];
    #pragma unroll
    for (int c = 0; c < 4;  c++) res[c] = fmaxf(out[c]*inv0 + bg[c], 0.f);
    #pragma unroll
    for (int c = 4; c < 8;  c++) res[c] = fmaxf(out[c]*inv1 + bg[c], 0.f);
    #pragma unroll
    for (int c = 8; c < 12; c++) res[c] = fmaxf(out[c]*inv2 + bg[c], 0.f);
    #pragma unroll
    for (int c = 12; c < 16; c++) res[c] = fmaxf(out[c]*inv3 + bg[c], 0.f);
    float4* pd = (float4*)g_p + ((size_t)b*NN + row2)*4;
    pd[0] = make_float4(res[0],res[1],res[2],res[3]);
    pd[1] = make_float4(res[4],res[5],res[6],res[7]);
    pd[2] = make_float4(res[8],res[9],res[10],res[11]);
    pd[3] = make_float4(res[12],res[13],res[14],res[15]);
}

// ---------- update MLP + fire + out conv + sigmoid ----------
__global__ void updk(const float* __restrict__ fire, const float* __restrict__ Wu1,
                     const float* __restrict__ bu1, const float* __restrict__ Wu2,
                     const float* __restrict__ bu2,
                     const float* __restrict__ Wo,  const float* __restrict__ bo)
{
    __shared__ __align__(16) float sW1[2048];
    __shared__ __align__(16) float sW2[2048];
    __shared__ float sb1[128], sb2[16], sWo[16];
    __shared__ float sbo;
    int t = threadIdx.x;
    for (int i = t; i < 2048; i += 256) {
        sW1[i] = Wu1[i];
        int h = i >> 4, o = i & 15;
        sW2[i] = Wu2[o*128 + h];
    }
    if (t < 128) sb1[t] = bu1[t];
    if (t < 16)  { sb2[t] = bu2[t]; sWo[t] = Wo[t]; }
    if (t == 0)  sbo = bo[0];
    __syncthreads();
    int idx = blockIdx.x * 256 + t;
    const float4* pp = (const float4*)(g_p + (size_t)idx*16);
    float4 p0 = pp[0], p1 = pp[1], p2 = pp[2], p3 = pp[3];
    float p[16];
    p[0]=p0.x; p[1]=p0.y; p[2]=p0.z; p[3]=p0.w;
    p[4]=p1.x; p[5]=p1.y; p[6]=p1.z; p[7]=p1.w;
    p[8]=p2.x; p[9]=p2.y; p[10]=p2.z; p[11]=p2.w;
    p[12]=p3.x; p[13]=p3.y; p[14]=p3.z; p[15]=p3.w;
    float u[16];
    #pragma unroll
    for (int o = 0; o < 16; o++) u[o] = sb2[o];
    #pragma unroll 2
    for (int h = 0; h < 128; h++) {
        float a = sb1[h];
        const float4* w1p = (const float4*)&sW1[h*16];
        float4 wa = w1p[0], wb = w1p[1], wc = w1p[2], wd = w1p[3];
        a = fmaf(p[0],wa.x,a); a = fmaf(p[1],wa.y,a); a = fmaf(p[2],wa.z,a); a = fmaf(p[3],wa.w,a);
        a = fmaf(p[4],wb.x,a); a = fmaf(p[5],wb.y,a); a = fmaf(p[6],wb.z,a); a = fmaf(p[7],wb.w,a);
        a = fmaf(p[8],wc.x,a); a = fmaf(p[9],wc.y,a); a = fmaf(p[10],wc.z,a); a = fmaf(p[11],wc.w,a);
        a = fmaf(p[12],wd.x,a); a = fmaf(p[13],wd.y,a); a = fmaf(p[14],wd.z,a); a = fmaf(p[15],wd.w,a);
        a = fmaxf(a, 0.f);
        const float4* w2p = (const float4*)&sW2[h*16];
        float4 va = w2p[0], vb = w2p[1], vc = w2p[2], vd = w2p[3];
        u[0]  = fmaf(a,va.x,u[0]);  u[1]  = fmaf(a,va.y,u[1]);
        u[2]  = fmaf(a,va.z,u[2]);  u[3]  = fmaf(a,va.w,u[3]);
        u[4]  = fmaf(a,vb.x,u[4]);  u[5]  = fmaf(a,vb.y,u[5]);
        u[6]  = fmaf(a,vb.z,u[6]);  u[7]  = fmaf(a,vb.w,u[7]);
        u[8]  = fmaf(a,vc.x,u[8]);  u[9]  = fmaf(a,vc.y,u[9]);
        u[10] = fmaf(a,vc.z,u[10]); u[11] = fmaf(a,vc.w,u[11]);
        u[12] = fmaf(a,vd.x,u[12]); u[13] = fmaf(a,vd.y,u[13]);
        u[14] = fmaf(a,vd.z,u[14]); u[15] = fmaf(a,vd.w,u[15]);
    }
    float mask = fire[idx] < 0.5f ? 1.f : 0.f;
    const float4* hp = (const float4*)(g_nodes + (size_t)idx*16);
    float4 h0 = hp[0], h1 = hp[1], h2 = hp[2], h3 = hp[3];
    float hh[16];
    hh[0]=h0.x; hh[1]=h0.y; hh[2]=h0.z; hh[3]=h0.w;
    hh[4]=h1.x; hh[5]=h1.y; hh[6]=h1.z; hh[7]=h1.w;
    hh[8]=h2.x; hh[9]=h2.y; hh[10]=h2.z; hh[11]=h2.w;
    hh[12]=h3.x; hh[13]=h3.y; hh[14]=h3.z; hh[15]=h3.w;
    float ss = sbo;
    #pragma unroll
    for (int c = 0; c < 16; c++) {
        float hn = fmaf(mask, u[c], hh[c]);
        ss = fmaf(sWo[c], hn, ss);
    }
    g_outlow[idx] = 1.f / (1.f + expf(-ss));
}

// ---------- bilinear 64 -> 256 ----------
__global__ void upk(float* __restrict__ out)
{
    int idx = blockIdx.x * 256 + threadIdx.x;
    int b = idx >> 16, oy = (idx >> 8) & 255, ox = idx & 255;
    float sy = (oy + 0.5f) * 0.25f - 0.5f;
    float sx = (ox + 0.5f) * 0.25f - 0.5f;
    int y0 = (int)floorf(sy); float fy = sy - (float)y0;
    int x0 = (int)floorf(sx); float fx = sx - (float)x0;
    float wy0 = 1.f - fy, wy1 = fy; int y1 = y0 + 1;
    float wx0 = 1.f - fx, wx1 = fx; int x1 = x0 + 1;
    if (y0 < 0)  { wy0 = 0.f; y0 = 0; }
    if (y1 > 63) { wy1 = 0.f; y1 = 63; }
    if (x0 < 0)  { wx0 = 0.f; x0 = 0; }
    if (x1 > 63) { wx1 = 0.f; x1 = 63; }
    const float* src = g_outlow + b * 4096;
    float v = wy0 * (wx0 * src[y0*64 + x0] + wx1 * src[y0*64 + x1])
            + wy1 * (wx0 * src[y1*64 + x0] + wx1 * src[y1*64 + x1]);
    out[idx] = v / ((wy0 + wy1) * (wx0 + wx1));
}

extern "C" void kernel_launch(void* const* d_in, const int* in_sizes, int n_in,
                              void* d_out, int out_size)
{
    (void)in_sizes; (void)n_in; (void)out_size;
    const float* x    = (const float*)d_in[0];
    const float* fire = (const float*)d_in[1];
    const float* W1   = (const float*)d_in[2];
    const float* b1   = (const float*)d_in[3];
    const float* g1   = (const float*)d_in[4];
    const float* be1  = (const float*)d_in[5];
    const float* m1   = (const float*)d_in[6];
    const float* v1   = (const float*)d_in[7];
    const float* W2   = (const float*)d_in[8];
    const float* b2   = (const float*)d_in[9];
    const float* g2   = (const float*)d_in[10];
    const float* be2  = (const float*)d_in[11];
    const float* m2   = (const float*)d_in[12];
    const float* v2   = (const float*)d_in[13];
    const float* Wg   = (const float*)d_in[14];
    const float* a_src= (const float*)d_in[15];
    const float* a_dst= (const float*)d_in[16];
    const float* bg   = (const float*)d_in[17];
    const float* Wu1  = (const float*)d_in[18];
    const float* bu1  = (const float*)d_in[19];
    const float* Wu2  = (const float*)d_in[20];
    const float* bu2  = (const float*)d_in[21];
    const float* Wo   = (const float*)d_in[22];
    const float* bo   = (const float*)d_in[23];
    float* out = (float*)d_out;

    downconv1k<<<dim3(16, NB), 256>>>(x, W1, b1, g1, be1, m1, v1);
    conv2k<<<dim3(16, 4, NB), 256>>>(W2, b2, g2, be2, m2, v2);
    featk<<<128, 256>>>(Wg, a_src, a_dst);
    knnk<<<dim3(32, NB), 256>>>(bg);
    updk<<<128, 256>>>(fire, Wu1, bu1, Wu2, bu2, Wo, bo);
    upk<<<2048, 256>>>(out);
}